// round 11
// baseline (speedup 1.0000x reference)
#include <cuda_runtime.h>
#include <cuda_fp16.h>
#include <cstdint>

// ---------------------------------------------------------------------------
// GRU via mma.sync (HMMA). 128 CTAs x 1024 thr (32 warps), 32 samples/CTA.
// R11: sample-QUARTER split — warp (wid&7, wid>>3) owns gate rows 16*(wid&7)
// and samples 8*(wid>>3)..+7 (N=8 MMAs). 2x warps at constant total work.
// x B-fragments built in registers from 2 LDG.64 (no SMEM x tile); biases in
// SMEM half4 table. whh1+whh2 SMEM-resident, wih2 streamed from L2.
// Double-buffered h1/h2, one 256-thread quarter barrier per step.
// ---------------------------------------------------------------------------

#define HID  128
#define MB   32
#define LSEQ 128
#define NCLS 24
#define NTHR 1024

// A-fragment arrays: [frag][lane] uint4, frag = mt*nkt + kt
__device__ uint4 g_wih1H[24 * 32], g_wih1L[24 * 32];   // K=16
__device__ uint4 g_whh1H[192 * 32];                    // -> SMEM resident
__device__ uint4 g_wih2H[192 * 32];                    // streamed from L2
__device__ uint4 g_whh2H[192 * 32];                    // -> SMEM resident

// SMEM byte offsets
#define S_WHH1  0        // whh1 hi frags (98304)
#define S_WHH2  98304    // whh2 hi frags (98304)
#define S_H1    196608   // 2 bufs x 8192 (32x128 fp16, swizzled)
#define S_H2    212992   // 2 bufs x 8192
#define S_BIAS  229376   // 128 j x 2 layers x half4 (2048)
#define SMEM_SZ 231424

__device__ __forceinline__ uint32_t smem_u32(const void* p) {
    uint32_t a;
    asm("{ .reg .u64 t; cvta.to.shared.u64 t, %1; cvt.u32.u64 %0, t; }"
        : "=r"(a) : "l"(p));
    return a;
}
__device__ __forceinline__ void ldm2(uint32_t& r0, uint32_t& r1, uint32_t a) {
    asm volatile("ldmatrix.sync.aligned.m8n8.x2.shared.b16 {%0,%1}, [%2];"
                 : "=r"(r0), "=r"(r1) : "r"(a));
}
__device__ __forceinline__ void mmaf(float* d, const uint4& a,
                                     uint32_t b0, uint32_t b1) {
    asm volatile("mma.sync.aligned.m16n8k16.row.col.f32.f16.f16.f32 "
                 "{%0,%1,%2,%3}, {%4,%5,%6,%7}, {%8,%9}, {%0,%1,%2,%3};"
                 : "+f"(d[0]), "+f"(d[1]), "+f"(d[2]), "+f"(d[3])
                 : "r"(a.x), "r"(a.y), "r"(a.z), "r"(a.w), "r"(b0), "r"(b1));
}
__device__ __forceinline__ float sigf(float v) { return 1.f / (1.f + __expf(-v)); }
__device__ __forceinline__ float tanhf_fast(float v) {
    v = fminf(fmaxf(v, -15.f), 15.f);
    float e = __expf(2.f * v);
    return (e - 1.f) / (e + 1.f);
}

// ---- prep: pack fp32 weights into per-lane A fragments --------------------
__global__ void prep_kernel(const float* __restrict__ w_ih1,
                            const float* __restrict__ w_hh1,
                            const float* __restrict__ w_ih2,
                            const float* __restrict__ w_hh2) {
    int t = blockIdx.x * blockDim.x + threadIdx.x;
    if (t >= 600 * 32) return;
    int f = t >> 5, lane = t & 31;
    const float* W; uint4* dh; uint4* dl = nullptr; int K, fl;
    if (f < 24)       { W = w_ih1; dh = g_wih1H; dl = g_wih1L; K = 16;  fl = f; }
    else if (f < 216) { W = w_hh1; dh = g_whh1H; K = 128; fl = f - 24; }
    else if (f < 408) { W = w_ih2; dh = g_wih2H; K = 128; fl = f - 216; }
    else              { W = w_hh2; dh = g_whh2H; K = 128; fl = f - 408; }
    int nkt = K >> 4;
    int mt = fl / nkt, kt = fl % nkt;
    int gid = lane >> 2, tig = lane & 3;
    int r0 = mt * 16 + gid, r1 = r0 + 8, c0 = kt * 16 + tig * 2;
    float2 v[4];
    v[0] = *(const float2*)(W + r0 * K + c0);
    v[1] = *(const float2*)(W + r1 * K + c0);
    v[2] = *(const float2*)(W + r0 * K + c0 + 8);
    v[3] = *(const float2*)(W + r1 * K + c0 + 8);
    uint4 oh, ol;
    uint32_t* ph = (uint32_t*)&oh;
    uint32_t* pl = (uint32_t*)&ol;
#pragma unroll
    for (int qq = 0; qq < 4; qq++) {
        __half2 hi = __floats2half2_rn(v[qq].x, v[qq].y);
        __half2 lo = __floats2half2_rn(v[qq].x - __half2float(__low2half(hi)),
                                       v[qq].y - __half2float(__high2half(hi)));
        ph[qq] = *(uint32_t*)&hi;
        pl[qq] = *(uint32_t*)&lo;
    }
    dh[fl * 32 + lane] = oh;
    if (dl) dl[fl * 32 + lane] = ol;
}

// ---------------------------------------------------------------------------
__global__ __launch_bounds__(NTHR, 1)
void gru_mma_kernel(const float* __restrict__ x,
                    const float* __restrict__ b_ih1, const float* __restrict__ b_hh1,
                    const float* __restrict__ b_ih2, const float* __restrict__ b_hh2,
                    const float* __restrict__ fc_w,  const float* __restrict__ fc_b,
                    float* __restrict__ out) {
    extern __shared__ char smem[];
    const uint32_t sb = smem_u32(smem);
    const int tid = threadIdx.x;
    const int wid = tid >> 5, lane = tid & 31;
    const int wpair = wid & 7;           // gate row-group (rows 16*wpair)
    const int q = wid >> 3;              // sample quarter (samples 8q..8q+7)
    const int b0 = blockIdx.x * MB;
    const int gid = lane >> 2, tig = lane & 3;
    const int lr = lane & 7, lh = (lane >> 3) & 1;
    const int xorv = lr << 4;
    const int wbase = wpair * 16;
    const int barid = 1 + q;

#define BARH() asm volatile("bar.sync %0, 256;" :: "r"(barid) : "memory")

    uint32_t h1rd = S_H1 + 8192, h1wr = S_H1;
    uint32_t h2rd = S_H2 + 8192, h2wr = S_H2;

    // ---- init: whh1+whh2 -> SMEM, zero h buffers, bias table ----
    {
        uint4* d1 = (uint4*)(smem + S_WHH1);
        uint4* d2 = (uint4*)(smem + S_WHH2);
        for (int i = tid; i < 192 * 32; i += NTHR) {
            d1[i] = g_whh1H[i];
            d2[i] = g_whh2H[i];
        }
        uint4 z4 = make_uint4(0, 0, 0, 0);
        uint4* hz = (uint4*)(smem + S_H1);
        for (int i = tid; i < 32768 / 16; i += NTHR) hz[i] = z4;
    }
    if (tid < 256) {
        int j = tid >> 1, layer = tid & 1;
        const float* bih = layer ? b_ih2 : b_ih1;
        const float* bhh = layer ? b_hh2 : b_hh1;
        __half2 p0 = __floats2half2_rn(bih[j] + bhh[j], bih[128 + j] + bhh[128 + j]);
        __half2 p1 = __floats2half2_rn(bih[256 + j], bhh[256 + j]);
        uint2 u;
        u.x = *(uint32_t*)&p0;
        u.y = *(uint32_t*)&p1;
        *(uint2*)(smem + S_BIAS + (j * 2 + layer) * 8) = u;
    }

    // x B-fragment (registers): sample q*8+gid, features (2tig,2tig+1 | +8)
    const float* xbase = x + (size_t)(b0 + q * 8 + gid) * 2048 + 2 * tig;
    uint32_t xb0, xb1;
    {
        float2 v0 = *(const float2*)(xbase);
        float2 v1 = *(const float2*)(xbase + 1024);
        __half2 p0 = __floats2half2_rn(v0.x, v0.y);
        __half2 p1 = __floats2half2_rn(v1.x, v1.y);
        xb0 = *(uint32_t*)&p0;
        xb1 = *(uint32_t*)&p1;
    }

    float h1reg[4], h2reg[4];
#pragma unroll
    for (int e = 0; e < 4; e++) { h1reg[e] = 0.f; h2reg[e] = 0.f; }
    float ar[4], az[4], ai[4], ah[4];
    __syncthreads();

#define ZERO_ACC() { _Pragma("unroll") for (int e_ = 0; e_ < 4; e_++) { \
        ar[e_] = 0.f; az[e_] = 0.f; ai[e_] = 0.f; ah[e_] = 0.f; } }

// epilogue: SMEM-bias fetch + gate math + h update + fp16 store (warp-local)
#define EPILOGUE(layer_, hreg_, hwr_) { \
    uint2 bu0 = *(uint2*)(smem + S_BIAS + ((wbase + gid) * 2 + (layer_)) * 8); \
    uint2 bu1 = *(uint2*)(smem + S_BIAS + ((wbase + gid + 8) * 2 + (layer_)) * 8); \
    float2 brz[2], bih[2]; \
    brz[0] = __half22float2(*(__half2*)&bu0.x); bih[0] = __half22float2(*(__half2*)&bu0.y); \
    brz[1] = __half22float2(*(__half2*)&bu1.x); bih[1] = __half22float2(*(__half2*)&bu1.y); \
    _Pragma("unroll") for (int e_ = 0; e_ < 4; e_++) { \
        int rowi_ = e_ >> 1; \
        int m_ = q * 8 + tig * 2 + (e_ & 1); \
        float r_ = sigf(ar[e_] + brz[rowi_].x); \
        float z_ = sigf(az[e_] + brz[rowi_].y); \
        float n_ = tanhf_fast(ai[e_] + bih[rowi_].x + r_ * (ah[e_] + bih[rowi_].y)); \
        float h_ = n_ + z_ * (hreg_[e_] - n_); \
        hreg_[e_] = h_; \
        int j_ = wbase + gid + rowi_ * 8; \
        uint32_t off_ = (hwr_) + m_ * 256 + ((2 * j_) ^ ((m_ & 7) << 4)); \
        *(__half*)(smem + off_) = __float2half_rn(h_); \
    } }

    const uint4* wf1 = (const uint4*)(smem + S_WHH1);
    const uint4* wf2 = (const uint4*)(smem + S_WHH2);

#pragma unroll 1
    for (int t = 0; t < LSEQ; t++) {
        ZERO_ACC();
        // ---- L1: x contribution (register B-frags; Whi*x then Wlo*x) ----
        {
            uint4 Ar = g_wih1H[wpair * 32 + lane];
            uint4 Az = g_wih1H[(8 + wpair) * 32 + lane];
            uint4 Ai = g_wih1H[(16 + wpair) * 32 + lane];
            mmaf(ar, Ar, xb0, xb1); mmaf(az, Az, xb0, xb1); mmaf(ai, Ai, xb0, xb1);
            uint4 Lr = g_wih1L[wpair * 32 + lane];
            uint4 Lz = g_wih1L[(8 + wpair) * 32 + lane];
            uint4 Li = g_wih1L[(16 + wpair) * 32 + lane];
            mmaf(ar, Lr, xb0, xb1); mmaf(az, Lz, xb0, xb1); mmaf(ai, Li, xb0, xb1);
        }
        // ---- L1: whh1 @ h1(t-1) (SMEM frags; B from h1rd) ----
#pragma unroll 2
        for (int kt = 0; kt < 8; kt++) {
            uint4 Ar = wf1[(wpair * 8 + kt) * 32 + lane];
            uint4 Az = wf1[((8 + wpair) * 8 + kt) * 32 + lane];
            uint4 An = wf1[((16 + wpair) * 8 + kt) * 32 + lane];
            uint32_t a = sb + h1rd + (q * 8 + lr) * 256
                       + (uint32_t)((kt * 32 + lh * 16) ^ xorv);
            uint32_t c0, c1;
            ldm2(c0, c1, a);
            mmaf(ar, Ar, c0, c1); mmaf(az, Az, c0, c1); mmaf(ah, An, c0, c1);
        }
        EPILOGUE(0, h1reg, h1wr);
        BARH();   // h1(t) visible within quarter; rest covered by parity
        // prefetch x(t+1) into registers (covered by whole L2 phase)
        {
            int tt = (t + 1 < LSEQ) ? t + 1 : t;
            float2 v0 = *(const float2*)(xbase + tt * 8);
            float2 v1 = *(const float2*)(xbase + 1024 + tt * 8);
            __half2 p0 = __floats2half2_rn(v0.x, v0.y);
            __half2 p1 = __floats2half2_rn(v1.x, v1.y);
            xb0 = *(uint32_t*)&p0;
            xb1 = *(uint32_t*)&p1;
        }
        // ---- L2: wih2(L2-stream) @ h1(t) + whh2(SMEM) @ h2(t-1) ----
        ZERO_ACC();
#pragma unroll 2
        for (int kt = 0; kt < 8; kt++) {
            uint4 Br = g_wih2H[(wpair * 8 + kt) * 32 + lane];
            uint4 Bz = g_wih2H[((8 + wpair) * 8 + kt) * 32 + lane];
            uint4 Bi = g_wih2H[((16 + wpair) * 8 + kt) * 32 + lane];
            uint32_t kb = (uint32_t)((kt * 32 + lh * 16) ^ xorv);
            // whh2 SMEM work first (covers the wih2 LDGs above)
            uint4 Cr = wf2[(wpair * 8 + kt) * 32 + lane];
            uint4 Cz = wf2[((8 + wpair) * 8 + kt) * 32 + lane];
            uint4 Cn = wf2[((16 + wpair) * 8 + kt) * 32 + lane];
            uint32_t a2 = sb + h2rd + (q * 8 + lr) * 256 + kb;
            uint32_t c0, c1;
            ldm2(c0, c1, a2);
            mmaf(ar, Cr, c0, c1); mmaf(az, Cz, c0, c1); mmaf(ah, Cn, c0, c1);
            uint32_t a1 = sb + h1wr + (q * 8 + lr) * 256 + kb;
            uint32_t d0, d1;
            ldm2(d0, d1, a1);
            mmaf(ar, Br, d0, d1); mmaf(az, Bz, d0, d1); mmaf(ai, Bi, d0, d1);
        }
        EPILOGUE(1, h2reg, h2wr);
        {
            uint32_t s;
            s = h1rd; h1rd = h1wr; h1wr = s;
            s = h2rd; h2rd = h2wr; h2wr = s;
        }
    }

    // ---- FC head ----
    __syncthreads();
    float* hs = (float*)smem;                  // [32][128] fp32 over weight region
#pragma unroll
    for (int e = 0; e < 4; e++) {
        int m = q * 8 + tig * 2 + (e & 1);
        int j = wbase + gid + (e >> 1) * 8;
        hs[m * 128 + j] = h2reg[e];
    }
    __syncthreads();
    if (tid < 768) {
        int m = tid / NCLS, c = tid - (tid / NCLS) * NCLS;
        float acc = fc_b[c];
#pragma unroll 4
        for (int k = 0; k < HID; k++)
            acc = fmaf(fc_w[c * HID + k], hs[m * 128 + k], acc);
        out[(size_t)(b0 + m) * NCLS + c] = acc;
    }
#undef BARH
#undef ZERO_ACC
#undef EPILOGUE
}

// ---------------------------------------------------------------------------
extern "C" void kernel_launch(void* const* d_in, const int* in_sizes, int n_in,
                              void* d_out, int out_size) {
    const float* x     = (const float*)d_in[0];
    const float* w_ih1 = (const float*)d_in[1];
    const float* w_hh1 = (const float*)d_in[2];
    const float* b_ih1 = (const float*)d_in[3];
    const float* b_hh1 = (const float*)d_in[4];
    const float* w_ih2 = (const float*)d_in[5];
    const float* w_hh2 = (const float*)d_in[6];
    const float* b_ih2 = (const float*)d_in[7];
    const float* b_hh2 = (const float*)d_in[8];
    const float* fc_w  = (const float*)d_in[9];
    const float* fc_b  = (const float*)d_in[10];
    float* out = (float*)d_out;

    cudaFuncSetAttribute(gru_mma_kernel,
                         cudaFuncAttributeMaxDynamicSharedMemorySize, SMEM_SZ);

    prep_kernel<<<75, 256>>>(w_ih1, w_hh1, w_ih2, w_hh2);
    gru_mma_kernel<<<4096 / MB, NTHR, SMEM_SZ>>>(x, b_ih1, b_hh1, b_ih2, b_hh2,
                                                 fc_w, fc_b, out);
}

// round 12
// speedup vs baseline: 1.1866x; 1.1866x over previous
#include <cuda_runtime.h>
#include <cuda_fp16.h>
#include <cstdint>

// ---------------------------------------------------------------------------
// GRU via mma.sync (HMMA). 128 CTAs x 512 thr (16 warps), 32 samples/CTA.
// R12: LAYER-specialized warp groups. Warps 0-7 (A) = layer 1 for all 32
// samples; warps 8-15 (B) = layer 2, lagged one timestep (computes h2(t-1)
// while A computes h1(t)). N=32 per warp (4 n-tiles) -> A-frag reload traffic
// halves vs R10. One __syncthreads per step; double-buffered h1/h2 tiles.
// ldmatrix.x4 B-frag loads; x B-frags in registers; h_old re-read from tile.
// Weights fp16 (wih1 keeps hi+lo); h/x single fp16.
// ---------------------------------------------------------------------------

#define HID  128
#define MB   32
#define LSEQ 128
#define NCLS 24
#define NTHR 512

// A-fragment arrays: [frag][lane] uint4, frag = mt*nkt + kt
__device__ uint4 g_wih1H[24 * 32], g_wih1L[24 * 32];   // K=16
__device__ uint4 g_whh1H[192 * 32];                    // -> SMEM resident
__device__ uint4 g_wih2H[192 * 32];                    // streamed from L2
__device__ uint4 g_whh2H[192 * 32];                    // -> SMEM resident

// SMEM byte offsets
#define S_WHH1  0        // whh1 hi frags (98304)
#define S_WHH2  98304    // whh2 hi frags (98304)
#define S_H1    196608   // 2 bufs x 8192 (32x128 fp16, swizzled)
#define S_H2    212992   // 2 bufs x 8192
#define S_BIAS  229376   // 128 j x 2 layers x half4 (2048)
#define SMEM_SZ 231424

__device__ __forceinline__ uint32_t smem_u32(const void* p) {
    uint32_t a;
    asm("{ .reg .u64 t; cvta.to.shared.u64 t, %1; cvt.u32.u64 %0, t; }"
        : "=r"(a) : "l"(p));
    return a;
}
__device__ __forceinline__ void ldm4(uint32_t& r0, uint32_t& r1,
                                     uint32_t& r2, uint32_t& r3, uint32_t a) {
    asm volatile("ldmatrix.sync.aligned.m8n8.x4.shared.b16 {%0,%1,%2,%3}, [%4];"
                 : "=r"(r0), "=r"(r1), "=r"(r2), "=r"(r3) : "r"(a));
}
__device__ __forceinline__ void mmaf(float* d, const uint4& a,
                                     uint32_t b0, uint32_t b1) {
    asm volatile("mma.sync.aligned.m16n8k16.row.col.f32.f16.f16.f32 "
                 "{%0,%1,%2,%3}, {%4,%5,%6,%7}, {%8,%9}, {%0,%1,%2,%3};"
                 : "+f"(d[0]), "+f"(d[1]), "+f"(d[2]), "+f"(d[3])
                 : "r"(a.x), "r"(a.y), "r"(a.z), "r"(a.w), "r"(b0), "r"(b1));
}
__device__ __forceinline__ float sigf(float v) { return 1.f / (1.f + __expf(-v)); }
__device__ __forceinline__ float tanhf_fast(float v) {
    v = fminf(fmaxf(v, -15.f), 15.f);
    float e = __expf(2.f * v);
    return (e - 1.f) / (e + 1.f);
}

// ---- prep: pack fp32 weights into per-lane A fragments --------------------
__global__ void prep_kernel(const float* __restrict__ w_ih1,
                            const float* __restrict__ w_hh1,
                            const float* __restrict__ w_ih2,
                            const float* __restrict__ w_hh2) {
    int t = blockIdx.x * blockDim.x + threadIdx.x;
    if (t >= 600 * 32) return;
    int f = t >> 5, lane = t & 31;
    const float* W; uint4* dh; uint4* dl = nullptr; int K, fl;
    if (f < 24)       { W = w_ih1; dh = g_wih1H; dl = g_wih1L; K = 16;  fl = f; }
    else if (f < 216) { W = w_hh1; dh = g_whh1H; K = 128; fl = f - 24; }
    else if (f < 408) { W = w_ih2; dh = g_wih2H; K = 128; fl = f - 216; }
    else              { W = w_hh2; dh = g_whh2H; K = 128; fl = f - 408; }
    int nkt = K >> 4;
    int mt = fl / nkt, kt = fl % nkt;
    int gid = lane >> 2, tig = lane & 3;
    int r0 = mt * 16 + gid, r1 = r0 + 8, c0 = kt * 16 + tig * 2;
    float2 v[4];
    v[0] = *(const float2*)(W + r0 * K + c0);
    v[1] = *(const float2*)(W + r1 * K + c0);
    v[2] = *(const float2*)(W + r0 * K + c0 + 8);
    v[3] = *(const float2*)(W + r1 * K + c0 + 8);
    uint4 oh, ol;
    uint32_t* ph = (uint32_t*)&oh;
    uint32_t* pl = (uint32_t*)&ol;
#pragma unroll
    for (int qq = 0; qq < 4; qq++) {
        __half2 hi = __floats2half2_rn(v[qq].x, v[qq].y);
        __half2 lo = __floats2half2_rn(v[qq].x - __half2float(__low2half(hi)),
                                       v[qq].y - __half2float(__high2half(hi)));
        ph[qq] = *(uint32_t*)&hi;
        pl[qq] = *(uint32_t*)&lo;
    }
    dh[fl * 32 + lane] = oh;
    if (dl) dl[fl * 32 + lane] = ol;
}

// ---------------------------------------------------------------------------
__global__ __launch_bounds__(NTHR, 1)
void gru_mma_kernel(const float* __restrict__ x,
                    const float* __restrict__ b_ih1, const float* __restrict__ b_hh1,
                    const float* __restrict__ b_ih2, const float* __restrict__ b_hh2,
                    const float* __restrict__ fc_w,  const float* __restrict__ fc_b,
                    float* __restrict__ out) {
    extern __shared__ char smem[];
    const uint32_t sb = smem_u32(smem);
    const int tid = threadIdx.x;
    const int wid = tid >> 5, lane = tid & 31;
    const int wpair = wid & 7;           // gate row-group (rows 16*wpair)
    const bool isA = (wid < 8);          // A: layer 1, B: layer 2 (lagged)
    const int b0 = blockIdx.x * MB;
    const int gid = lane >> 2, tig = lane & 3;
    const int lr = lane & 7, lh = (lane >> 3) & 1;
    const int nsel = lane >> 4;          // n-tile select within ldm4 pair
    const int xorv = lr << 4;
    const int wbase = wpair * 16;

    uint32_t h1rd = S_H1 + 8192, h1wr = S_H1;
    uint32_t h2rd = S_H2 + 8192, h2wr = S_H2;

    // ---- init: whh1+whh2 -> SMEM, zero h buffers, bias table ----
    {
        uint4* d1 = (uint4*)(smem + S_WHH1);
        uint4* d2 = (uint4*)(smem + S_WHH2);
        for (int i = tid; i < 192 * 32; i += NTHR) {
            d1[i] = g_whh1H[i];
            d2[i] = g_whh2H[i];
        }
        uint4 z4 = make_uint4(0, 0, 0, 0);
        uint4* hz = (uint4*)(smem + S_H1);
        for (int i = tid; i < 32768 / 16; i += NTHR) hz[i] = z4;
    }
    if (tid < 256) {
        int j = tid >> 1, layer = tid & 1;
        const float* bih = layer ? b_ih2 : b_ih1;
        const float* bhh = layer ? b_hh2 : b_hh1;
        __half2 p0 = __floats2half2_rn(bih[j] + bhh[j], bih[128 + j] + bhh[128 + j]);
        __half2 p1 = __floats2half2_rn(bih[256 + j], bhh[256 + j]);
        uint2 u;
        u.x = *(uint32_t*)&p0;
        u.y = *(uint32_t*)&p1;
        *(uint2*)(smem + S_BIAS + (j * 2 + layer) * 8) = u;
    }

    // x B-fragments in registers (A warps): sample nt*8+gid, feat 2tig(+8)
    const float* xA = x + (size_t)(b0 + gid) * 2048 + 2 * tig;
    uint32_t xb0[4], xb1[4];
    if (isA) {
#pragma unroll
        for (int nt = 0; nt < 4; nt++) {
            const float* p = xA + nt * 16384;
            float2 v0 = *(const float2*)(p);
            float2 v1 = *(const float2*)(p + 1024);
            __half2 q0 = __floats2half2_rn(v0.x, v0.y);
            __half2 q1 = __floats2half2_rn(v1.x, v1.y);
            xb0[nt] = *(uint32_t*)&q0;
            xb1[nt] = *(uint32_t*)&q1;
        }
    }

    float ar[4][4], az[4][4], ai[4][4], ah[4][4];
    __syncthreads();

#define ZERO_ACC() { _Pragma("unroll") for (int n_ = 0; n_ < 4; n_++) \
    _Pragma("unroll") for (int e_ = 0; e_ < 4; e_++) { \
        ar[n_][e_] = 0.f; az[n_][e_] = 0.f; ai[n_][e_] = 0.f; ah[n_][e_] = 0.f; } }

// gate math + h update; h_old read from rd tile, result to wr tile
#define EPILOGUE(layer_, hrd_, hwr_) { \
    uint2 bu0 = *(uint2*)(smem + S_BIAS + ((wbase + gid) * 2 + (layer_)) * 8); \
    uint2 bu1 = *(uint2*)(smem + S_BIAS + ((wbase + gid + 8) * 2 + (layer_)) * 8); \
    float2 brz[2], bih[2]; \
    brz[0] = __half22float2(*(__half2*)&bu0.x); bih[0] = __half22float2(*(__half2*)&bu0.y); \
    brz[1] = __half22float2(*(__half2*)&bu1.x); bih[1] = __half22float2(*(__half2*)&bu1.y); \
    _Pragma("unroll") for (int nt_ = 0; nt_ < 4; nt_++) \
    _Pragma("unroll") for (int e_ = 0; e_ < 4; e_++) { \
        int rowi_ = e_ >> 1; \
        int m_ = nt_ * 8 + tig * 2 + (e_ & 1); \
        int j_ = wbase + gid + rowi_ * 8; \
        uint32_t off_ = m_ * 256 + ((2 * j_) ^ ((m_ & 7) << 4)); \
        float hold_ = __half2float(*(__half*)(smem + (hrd_) + off_)); \
        float r_ = sigf(ar[nt_][e_] + brz[rowi_].x); \
        float z_ = sigf(az[nt_][e_] + brz[rowi_].y); \
        float n_ = tanhf_fast(ai[nt_][e_] + bih[rowi_].x + r_ * (ah[nt_][e_] + bih[rowi_].y)); \
        float h_ = n_ + z_ * (hold_ - n_); \
        *(__half*)(smem + (hwr_) + off_) = __float2half_rn(h_); \
    } }

    const uint4* wf1 = (const uint4*)(smem + S_WHH1);
    const uint4* wf2 = (const uint4*)(smem + S_WHH2);

#pragma unroll 1
    for (int t = 0; t <= LSEQ; t++) {
        if (isA) {
            if (t < LSEQ) {
                // ===== layer 1: h1(t) from h1(t-1)[h1rd] + x(t) =====
                ZERO_ACC();
                {   // x contribution (register B-frags)
                    uint4 Ar = g_wih1H[wpair * 32 + lane];
                    uint4 Az = g_wih1H[(8 + wpair) * 32 + lane];
                    uint4 Ai = g_wih1H[(16 + wpair) * 32 + lane];
                    uint4 Lr = g_wih1L[wpair * 32 + lane];
                    uint4 Lz = g_wih1L[(8 + wpair) * 32 + lane];
                    uint4 Li = g_wih1L[(16 + wpair) * 32 + lane];
#pragma unroll
                    for (int nt = 0; nt < 4; nt++) {
                        mmaf(ar[nt], Ar, xb0[nt], xb1[nt]);
                        mmaf(az[nt], Az, xb0[nt], xb1[nt]);
                        mmaf(ai[nt], Ai, xb0[nt], xb1[nt]);
                        mmaf(ar[nt], Lr, xb0[nt], xb1[nt]);
                        mmaf(az[nt], Lz, xb0[nt], xb1[nt]);
                        mmaf(ai[nt], Li, xb0[nt], xb1[nt]);
                    }
                }
                // whh1 @ h1(t-1)
#pragma unroll 2
                for (int kt = 0; kt < 8; kt++) {
                    uint4 Wr = wf1[(wpair * 8 + kt) * 32 + lane];
                    uint4 Wz = wf1[((8 + wpair) * 8 + kt) * 32 + lane];
                    uint4 Wn = wf1[((16 + wpair) * 8 + kt) * 32 + lane];
                    uint32_t kb = (uint32_t)((kt * 32 + lh * 16) ^ xorv);
#pragma unroll
                    for (int ntp = 0; ntp < 2; ntp++) {
                        uint32_t a = sb + h1rd
                                   + (uint32_t)(((ntp * 2 + nsel) * 8 + lr) * 256) + kb;
                        uint32_t c0, c1, c2, c3;
                        ldm4(c0, c1, c2, c3, a);
                        int n0 = ntp * 2, n1 = n0 + 1;
                        mmaf(ar[n0], Wr, c0, c1); mmaf(az[n0], Wz, c0, c1); mmaf(ah[n0], Wn, c0, c1);
                        mmaf(ar[n1], Wr, c2, c3); mmaf(az[n1], Wz, c2, c3); mmaf(ah[n1], Wn, c2, c3);
                    }
                }
                EPILOGUE(0, h1rd, h1wr);
                // prefetch x(t+1)
                {
                    int tt = (t + 1 < LSEQ) ? t + 1 : t;
#pragma unroll
                    for (int nt = 0; nt < 4; nt++) {
                        const float* p = xA + nt * 16384 + tt * 8;
                        float2 v0 = *(const float2*)(p);
                        float2 v1 = *(const float2*)(p + 1024);
                        __half2 q0 = __floats2half2_rn(v0.x, v0.y);
                        __half2 q1 = __floats2half2_rn(v1.x, v1.y);
                        xb0[nt] = *(uint32_t*)&q0;
                        xb1[nt] = *(uint32_t*)&q1;
                    }
                }
            }
        } else {
            if (t >= 1) {
                // ===== layer 2: h2(t-1) from h2(t-2)[h2rd] + h1(t-1)[h1rd] ==
                ZERO_ACC();
#pragma unroll 2
                for (int kt = 0; kt < 8; kt++) {
                    uint4 Br = g_wih2H[(wpair * 8 + kt) * 32 + lane];
                    uint4 Bz = g_wih2H[((8 + wpair) * 8 + kt) * 32 + lane];
                    uint4 Bi = g_wih2H[((16 + wpair) * 8 + kt) * 32 + lane];
                    uint4 Cr = wf2[(wpair * 8 + kt) * 32 + lane];
                    uint4 Cz = wf2[((8 + wpair) * 8 + kt) * 32 + lane];
                    uint4 Cn = wf2[((16 + wpair) * 8 + kt) * 32 + lane];
                    uint32_t kb = (uint32_t)((kt * 32 + lh * 16) ^ xorv);
#pragma unroll
                    for (int ntp = 0; ntp < 2; ntp++) {
                        uint32_t ridx = (uint32_t)(((ntp * 2 + nsel) * 8 + lr) * 256) + kb;
                        int n0 = ntp * 2, n1 = n0 + 1;
                        uint32_t c0, c1, c2, c3;
                        ldm4(c0, c1, c2, c3, sb + h2rd + ridx);      // h2(t-2)
                        mmaf(ar[n0], Cr, c0, c1); mmaf(az[n0], Cz, c0, c1); mmaf(ah[n0], Cn, c0, c1);
                        mmaf(ar[n1], Cr, c2, c3); mmaf(az[n1], Cz, c2, c3); mmaf(ah[n1], Cn, c2, c3);
                        uint32_t d0, d1, d2, d3;
                        ldm4(d0, d1, d2, d3, sb + h1rd + ridx);      // h1(t-1)
                        mmaf(ar[n0], Br, d0, d1); mmaf(az[n0], Bz, d0, d1); mmaf(ai[n0], Bi, d0, d1);
                        mmaf(ar[n1], Br, d2, d3); mmaf(az[n1], Bz, d2, d3); mmaf(ai[n1], Bi, d2, d3);
                    }
                }
                EPILOGUE(1, h2rd, h2wr);
            }
        }
        __syncthreads();
        {
            uint32_t s;
            s = h1rd; h1rd = h1wr; h1wr = s;
            s = h2rd; h2rd = h2wr; h2wr = s;
        }
    }

    // ---- FC head: read final h2 (fp16) from h2rd tile ----
    for (int o = tid; o < MB * NCLS; o += NTHR) {
        int m = o / NCLS, c = o - (o / NCLS) * NCLS;
        float acc = fc_b[c];
        uint32_t rowb = h2rd + m * 256;
        int sw = (m & 7) << 4;
#pragma unroll 4
        for (int k = 0; k < HID; k++) {
            float hv = __half2float(*(__half*)(smem + rowb + ((2 * k) ^ sw)));
            acc = fmaf(fc_w[c * HID + k], hv, acc);
        }
        out[(size_t)(b0 + m) * NCLS + c] = acc;
    }
#undef ZERO_ACC
#undef EPILOGUE
}

// ---------------------------------------------------------------------------
extern "C" void kernel_launch(void* const* d_in, const int* in_sizes, int n_in,
                              void* d_out, int out_size) {
    const float* x     = (const float*)d_in[0];
    const float* w_ih1 = (const float*)d_in[1];
    const float* w_hh1 = (const float*)d_in[2];
    const float* b_ih1 = (const float*)d_in[3];
    const float* b_hh1 = (const float*)d_in[4];
    const float* w_ih2 = (const float*)d_in[5];
    const float* w_hh2 = (const float*)d_in[6];
    const float* b_ih2 = (const float*)d_in[7];
    const float* b_hh2 = (const float*)d_in[8];
    const float* fc_w  = (const float*)d_in[9];
    const float* fc_b  = (const float*)d_in[10];
    float* out = (float*)d_out;

    cudaFuncSetAttribute(gru_mma_kernel,
                         cudaFuncAttributeMaxDynamicSharedMemorySize, SMEM_SZ);

    prep_kernel<<<75, 256>>>(w_ih1, w_hh1, w_ih2, w_hh2);
    gru_mma_kernel<<<4096 / MB, NTHR, SMEM_SZ>>>(x, b_ih1, b_hh1, b_ih2, b_hh2,
                                                 fc_w, fc_b, out);
}

// round 13
// speedup vs baseline: 1.4224x; 1.1988x over previous
#include <cuda_runtime.h>
#include <cuda_fp16.h>
#include <cstdint>

// ---------------------------------------------------------------------------
// GRU via mma.sync (HMMA). 128 CTAs x 512 thr (16 warps), 32 samples/CTA.
// R13: memory-home fix. SMEM shrunk 226->132 KB so L1D=96 KB: whh2 frags
// SMEM-resident, whh1 frags L1-cached LDG, wih1/wih2 via __ldcg (L2) with
// next-kt software prefetch. ldmatrix.x4; tanh.approx sigmoids; fp32 bias.
// Warp (wid&7, wid>>3): gate rows 16*(wid&7), samples 16*(wid>>3)..+15.
// Double-buffered h1/h2, one 256-thread half-barrier per step, h in regs.
// ---------------------------------------------------------------------------

#define HID  128
#define MB   32
#define LSEQ 128
#define NCLS 24
#define NTHR 512

// A-fragment arrays: [frag][lane] uint4, frag = mt*nkt + kt
__device__ uint4 g_wih1H[24 * 32];     // K=16, streamed via .cg
__device__ uint4 g_whh1H[192 * 32];    // streamed via L1-cached LDG
__device__ uint4 g_wih2H[192 * 32];    // streamed via .cg (prefetched)
__device__ uint4 g_whh2H[192 * 32];    // -> SMEM resident

// SMEM byte offsets
#define S_WHH2  0        // whh2 hi frags (98304)
#define S_H1    98304    // 2 bufs x 8192 (32x128 fp16, swizzled)
#define S_H2    114688   // 2 bufs x 8192
#define S_BIAS  131072   // 128 j x 2 layers x float4 (4096)
#define SMEM_SZ 135168   // = 132 KB exactly -> L1D carveout 96 KB

__device__ __forceinline__ uint32_t smem_u32(const void* p) {
    uint32_t a;
    asm("{ .reg .u64 t; cvta.to.shared.u64 t, %1; cvt.u32.u64 %0, t; }"
        : "=r"(a) : "l"(p));
    return a;
}
__device__ __forceinline__ void ldm4(uint32_t& r0, uint32_t& r1,
                                     uint32_t& r2, uint32_t& r3, uint32_t a) {
    asm volatile("ldmatrix.sync.aligned.m8n8.x4.shared.b16 {%0,%1,%2,%3}, [%4];"
                 : "=r"(r0), "=r"(r1), "=r"(r2), "=r"(r3) : "r"(a));
}
__device__ __forceinline__ void mmaf(float* d, const uint4& a,
                                     uint32_t b0, uint32_t b1) {
    asm volatile("mma.sync.aligned.m16n8k16.row.col.f32.f16.f16.f32 "
                 "{%0,%1,%2,%3}, {%4,%5,%6,%7}, {%8,%9}, {%0,%1,%2,%3};"
                 : "+f"(d[0]), "+f"(d[1]), "+f"(d[2]), "+f"(d[3])
                 : "r"(a.x), "r"(a.y), "r"(a.z), "r"(a.w), "r"(b0), "r"(b1));
}
__device__ __forceinline__ float sig_apx(float v) {
    float t;
    asm("tanh.approx.f32 %0, %1;" : "=f"(t) : "f"(v * 0.5f));
    return fmaf(t, 0.5f, 0.5f);
}
__device__ __forceinline__ float tanh_fast(float v) {
    v = fminf(fmaxf(v, -15.f), 15.f);
    float e = __expf(2.f * v);
    return (e - 1.f) / (e + 1.f);
}

// ---- prep: pack fp32 weights into per-lane fp16 A fragments ---------------
__global__ void prep_kernel(const float* __restrict__ w_ih1,
                            const float* __restrict__ w_hh1,
                            const float* __restrict__ w_ih2,
                            const float* __restrict__ w_hh2) {
    int t = blockIdx.x * blockDim.x + threadIdx.x;
    if (t >= 600 * 32) return;
    int f = t >> 5, lane = t & 31;
    const float* W; uint4* dh; int K, fl;
    if (f < 24)       { W = w_ih1; dh = g_wih1H; K = 16;  fl = f; }
    else if (f < 216) { W = w_hh1; dh = g_whh1H; K = 128; fl = f - 24; }
    else if (f < 408) { W = w_ih2; dh = g_wih2H; K = 128; fl = f - 216; }
    else              { W = w_hh2; dh = g_whh2H; K = 128; fl = f - 408; }
    int nkt = K >> 4;
    int mt = fl / nkt, kt = fl % nkt;
    int gid = lane >> 2, tig = lane & 3;
    int r0 = mt * 16 + gid, r1 = r0 + 8, c0 = kt * 16 + tig * 2;
    float2 v[4];
    v[0] = *(const float2*)(W + r0 * K + c0);
    v[1] = *(const float2*)(W + r1 * K + c0);
    v[2] = *(const float2*)(W + r0 * K + c0 + 8);
    v[3] = *(const float2*)(W + r1 * K + c0 + 8);
    uint4 oh;
    uint32_t* ph = (uint32_t*)&oh;
#pragma unroll
    for (int qq = 0; qq < 4; qq++) {
        __half2 hi = __floats2half2_rn(v[qq].x, v[qq].y);
        ph[qq] = *(uint32_t*)&hi;
    }
    dh[fl * 32 + lane] = oh;
}

// ---------------------------------------------------------------------------
__global__ __launch_bounds__(NTHR, 1)
void gru_mma_kernel(const float* __restrict__ x,
                    const float* __restrict__ b_ih1, const float* __restrict__ b_hh1,
                    const float* __restrict__ b_ih2, const float* __restrict__ b_hh2,
                    const float* __restrict__ fc_w,  const float* __restrict__ fc_b,
                    float* __restrict__ out) {
    extern __shared__ char smem[];
    const uint32_t sb = smem_u32(smem);
    const int tid = threadIdx.x;
    const int wid = tid >> 5, lane = tid & 31;
    const int wpair = wid & 7;           // gate row-group (rows 16*wpair)
    const int shalf = wid >> 3;          // sample half
    const int b0 = blockIdx.x * MB;
    const int gid = lane >> 2, tig = lane & 3;
    const int lr = lane & 7, lh = (lane >> 3) & 1;
    const int nsel = lane >> 4;
    const int xorv = lr << 4;
    const int wbase = wpair * 16;
    const int ntb = shalf * 2;           // this warp's two n-tiles
    const int barid = 1 + shalf;

#define BARH() asm volatile("bar.sync %0, 256;" :: "r"(barid) : "memory")

    uint32_t h1rd = S_H1 + 8192, h1wr = S_H1;
    uint32_t h2rd = S_H2 + 8192, h2wr = S_H2;

    // ---- init: whh2 -> SMEM, zero h buffers, fp32 bias table ----
    {
        uint4* d2 = (uint4*)(smem + S_WHH2);
        for (int i = tid; i < 192 * 32; i += NTHR) d2[i] = g_whh2H[i];
        uint4 z4 = make_uint4(0, 0, 0, 0);
        uint4* hz = (uint4*)(smem + S_H1);
        for (int i = tid; i < 32768 / 16; i += NTHR) hz[i] = z4;
    }
    if (tid < 256) {
        int j = tid >> 1, layer = tid & 1;
        const float* bih = layer ? b_ih2 : b_ih1;
        const float* bhh = layer ? b_hh2 : b_hh1;
        float4 bb = make_float4(bih[j] + bhh[j], bih[128 + j] + bhh[128 + j],
                                bih[256 + j], bhh[256 + j]);
        *(float4*)(smem + S_BIAS + (j * 2 + layer) * 16) = bb;
    }

    // x B-fragments in registers: tile ntb+ntl, sample (ntb+ntl)*8+gid
    const float* xA = x + (size_t)(b0 + ntb * 8 + gid) * 2048 + 2 * tig;
    uint32_t xb0[2], xb1[2];
#pragma unroll
    for (int ntl = 0; ntl < 2; ntl++) {
        const float* p = xA + ntl * 16384;
        float2 v0 = *(const float2*)(p);
        float2 v1 = *(const float2*)(p + 1024);
        __half2 q0 = __floats2half2_rn(v0.x, v0.y);
        __half2 q1 = __floats2half2_rn(v1.x, v1.y);
        xb0[ntl] = *(uint32_t*)&q0;
        xb1[ntl] = *(uint32_t*)&q1;
    }

    float h1reg[8], h2reg[8];
#pragma unroll
    for (int e = 0; e < 8; e++) { h1reg[e] = 0.f; h2reg[e] = 0.f; }
    float ar[2][4], az[2][4], ai[2][4], ah[2][4];
    __syncthreads();

#define ZERO_ACC() { _Pragma("unroll") for (int n_ = 0; n_ < 2; n_++) \
    _Pragma("unroll") for (int e_ = 0; e_ < 4; e_++) { \
        ar[n_][e_] = 0.f; az[n_][e_] = 0.f; ai[n_][e_] = 0.f; ah[n_][e_] = 0.f; } }

// gate math + h update (h_old in regs) + fp16 store to hwr_
#define EPILOGUE(layer_, hreg_, hwr_) { \
    float4 bb0 = *(float4*)(smem + S_BIAS + ((wbase + gid) * 2 + (layer_)) * 16); \
    float4 bb1 = *(float4*)(smem + S_BIAS + ((wbase + gid + 8) * 2 + (layer_)) * 16); \
    _Pragma("unroll") for (int ntl = 0; ntl < 2; ntl++) \
    _Pragma("unroll") for (int e_ = 0; e_ < 4; e_++) { \
        const float4& bb = (e_ >> 1) ? bb1 : bb0; \
        int m_ = (ntb + ntl) * 8 + tig * 2 + (e_ & 1); \
        float r_ = sig_apx(ar[ntl][e_] + bb.x); \
        float z_ = sig_apx(az[ntl][e_] + bb.y); \
        float n_ = tanh_fast(fmaf(r_, ah[ntl][e_] + bb.w, ai[ntl][e_] + bb.z)); \
        int idx_ = ntl * 4 + e_; \
        float h_ = n_ + z_ * (hreg_[idx_] - n_); \
        hreg_[idx_] = h_; \
        int j_ = wbase + gid + (e_ >> 1) * 8; \
        uint32_t off_ = (hwr_) + m_ * 256 + ((2 * j_) ^ ((m_ & 7) << 4)); \
        *(__half*)(smem + off_) = __float2half_rn(h_); \
    } }

    const uint4* wf2 = (const uint4*)(smem + S_WHH2);

#pragma unroll 1
    for (int t = 0; t < LSEQ; t++) {
        ZERO_ACC();
        // ---- L1: wih1 @ x (frags via .cg; covered by whh1 section) ----
        {
            uint4 Ar = __ldcg(&g_wih1H[wpair * 32 + lane]);
            uint4 Az = __ldcg(&g_wih1H[(8 + wpair) * 32 + lane]);
            uint4 Ai = __ldcg(&g_wih1H[(16 + wpair) * 32 + lane]);
#pragma unroll
            for (int ntl = 0; ntl < 2; ntl++) {
                mmaf(ar[ntl], Ar, xb0[ntl], xb1[ntl]);
                mmaf(az[ntl], Az, xb0[ntl], xb1[ntl]);
                mmaf(ai[ntl], Ai, xb0[ntl], xb1[ntl]);
            }
        }
        // ---- L1: whh1 @ h1(t-1) (L1-cached LDG frags; B from h1rd) ----
#pragma unroll 2
        for (int kt = 0; kt < 8; kt++) {
            uint4 Wr = g_whh1H[(wpair * 8 + kt) * 32 + lane];
            uint4 Wz = g_whh1H[((8 + wpair) * 8 + kt) * 32 + lane];
            uint4 Wn = g_whh1H[((16 + wpair) * 8 + kt) * 32 + lane];
            uint32_t a = sb + h1rd + (uint32_t)(((ntb + nsel) * 8 + lr) * 256)
                       + (uint32_t)((kt * 32 + lh * 16) ^ xorv);
            uint32_t c0, c1, c2, c3;
            ldm4(c0, c1, c2, c3, a);
            mmaf(ar[0], Wr, c0, c1); mmaf(az[0], Wz, c0, c1); mmaf(ah[0], Wn, c0, c1);
            mmaf(ar[1], Wr, c2, c3); mmaf(az[1], Wz, c2, c3); mmaf(ah[1], Wn, c2, c3);
        }
        EPILOGUE(0, h1reg, h1wr);
        // prefetch x(t+1) into registers
        {
            int tt = (t + 1 < LSEQ) ? t + 1 : t;
#pragma unroll
            for (int ntl = 0; ntl < 2; ntl++) {
                const float* p = xA + ntl * 16384 + tt * 8;
                float2 v0 = *(const float2*)(p);
                float2 v1 = *(const float2*)(p + 1024);
                __half2 q0 = __floats2half2_rn(v0.x, v0.y);
                __half2 q1 = __floats2half2_rn(v1.x, v1.y);
                xb0[ntl] = *(uint32_t*)&q0;
                xb1[ntl] = *(uint32_t*)&q1;
            }
        }
        BARH();   // h1(t) visible within half; rest covered by buffer parity

        // ---- L2: wih2(.cg, prefetched) @ h1(t) + whh2(SMEM) @ h2(t-1) ----
        ZERO_ACC();
        uint4 Br = __ldcg(&g_wih2H[(wpair * 8) * 32 + lane]);
        uint4 Bz = __ldcg(&g_wih2H[((8 + wpair) * 8) * 32 + lane]);
        uint4 Bi = __ldcg(&g_wih2H[((16 + wpair) * 8) * 32 + lane]);
#pragma unroll 2
        for (int kt = 0; kt < 8; kt++) {
            uint4 Nr, Nz, Ni;
            if (kt < 7) {
                Nr = __ldcg(&g_wih2H[(wpair * 8 + kt + 1) * 32 + lane]);
                Nz = __ldcg(&g_wih2H[((8 + wpair) * 8 + kt + 1) * 32 + lane]);
                Ni = __ldcg(&g_wih2H[((16 + wpair) * 8 + kt + 1) * 32 + lane]);
            }
            uint4 Cr = wf2[(wpair * 8 + kt) * 32 + lane];
            uint4 Cz = wf2[((8 + wpair) * 8 + kt) * 32 + lane];
            uint4 Cn = wf2[((16 + wpair) * 8 + kt) * 32 + lane];
            uint32_t rsel = (uint32_t)(((ntb + nsel) * 8 + lr) * 256)
                          + (uint32_t)((kt * 32 + lh * 16) ^ xorv);
            uint32_t c0, c1, c2, c3;
            ldm4(c0, c1, c2, c3, sb + h2rd + rsel);     // h2(t-1)
            mmaf(ar[0], Cr, c0, c1); mmaf(az[0], Cz, c0, c1); mmaf(ah[0], Cn, c0, c1);
            mmaf(ar[1], Cr, c2, c3); mmaf(az[1], Cz, c2, c3); mmaf(ah[1], Cn, c2, c3);
            uint32_t d0, d1, d2, d3;
            ldm4(d0, d1, d2, d3, sb + h1wr + rsel);     // h1(t)
            mmaf(ar[0], Br, d0, d1); mmaf(az[0], Bz, d0, d1); mmaf(ai[0], Bi, d0, d1);
            mmaf(ar[1], Br, d2, d3); mmaf(az[1], Bz, d2, d3); mmaf(ai[1], Bi, d2, d3);
            if (kt < 7) { Br = Nr; Bz = Nz; Bi = Ni; }
        }
        EPILOGUE(1, h2reg, h2wr);
        {
            uint32_t s;
            s = h1rd; h1rd = h1wr; h1wr = s;
            s = h2rd; h2rd = h2wr; h2wr = s;
        }
    }

    // ---- FC head ----
    __syncthreads();
    float* hs = (float*)smem;                  // [32][128] fp32 over whh2 region
#pragma unroll
    for (int ntl = 0; ntl < 2; ntl++)
#pragma unroll
        for (int e = 0; e < 4; e++) {
            int m = (ntb + ntl) * 8 + tig * 2 + (e & 1);
            int j = wbase + gid + (e >> 1) * 8;
            hs[m * 128 + j] = h2reg[ntl * 4 + e];
        }
    __syncthreads();
    if (tid < 256) {
        int o0 = tid * 3;
#pragma unroll
        for (int o = o0; o < o0 + 3; o++) {
            int m = o / NCLS, c = o - (o / NCLS) * NCLS;
            float acc = fc_b[c];
#pragma unroll 4
            for (int k = 0; k < HID; k++)
                acc = fmaf(fc_w[c * HID + k], hs[m * 128 + k], acc);
            out[(size_t)(b0 + m) * NCLS + c] = acc;
        }
    }
#undef BARH
#undef ZERO_ACC
#undef EPILOGUE
}

// ---------------------------------------------------------------------------
extern "C" void kernel_launch(void* const* d_in, const int* in_sizes, int n_in,
                              void* d_out, int out_size) {
    const float* x     = (const float*)d_in[0];
    const float* w_ih1 = (const float*)d_in[1];
    const float* w_hh1 = (const float*)d_in[2];
    const float* b_ih1 = (const float*)d_in[3];
    const float* b_hh1 = (const float*)d_in[4];
    const float* w_ih2 = (const float*)d_in[5];
    const float* w_hh2 = (const float*)d_in[6];
    const float* b_ih2 = (const float*)d_in[7];
    const float* b_hh2 = (const float*)d_in[8];
    const float* fc_w  = (const float*)d_in[9];
    const float* fc_b  = (const float*)d_in[10];
    float* out = (float*)d_out;

    cudaFuncSetAttribute(gru_mma_kernel,
                         cudaFuncAttributeMaxDynamicSharedMemorySize, SMEM_SZ);

    prep_kernel<<<75, 256>>>(w_ih1, w_hh1, w_ih2, w_hh2);
    gru_mma_kernel<<<4096 / MB, NTHR, SMEM_SZ>>>(x, b_ih1, b_hh1, b_ih2, b_hh2,
                                                 fc_w, fc_b, out);
}

// round 14
// speedup vs baseline: 1.5923x; 1.1194x over previous
#include <cuda_runtime.h>
#include <cuda_fp16.h>
#include <cstdint>

// ---------------------------------------------------------------------------
// GRU via mma.sync (HMMA). 128 CTAs x 512 thr (16 warps), 32 samples/CTA.
// R14 (on R13's memory homes): (1) epilogue tanh via __fdividef — removes
// div.rn.f32 subroutine from the serial chain; (2) whh2@h2(t-1) MMA block
// hoisted into the barrier shadow (2 half-barriers/step, ~1/3 fewer MMAs on
// the inter-barrier critical path); wih1 loads L1-cached + latency-covered.
// SMEM 132KB -> L1D 96KB: whh2 SMEM-resident, whh1 L1-cached LDG, wih2 .cg.
// ---------------------------------------------------------------------------

#define HID  128
#define MB   32
#define LSEQ 128
#define NCLS 24
#define NTHR 512

// A-fragment arrays: [frag][lane] uint4, frag = mt*nkt + kt
__device__ uint4 g_wih1H[24 * 32];     // K=16, L1-cached LDG
__device__ uint4 g_whh1H[192 * 32];    // L1-cached LDG (fits 96KB L1D)
__device__ uint4 g_wih2H[192 * 32];    // streamed via .cg (prefetched)
__device__ uint4 g_whh2H[192 * 32];    // -> SMEM resident

// SMEM byte offsets
#define S_WHH2  0        // whh2 hi frags (98304)
#define S_H1    98304    // 2 bufs x 8192 (32x128 fp16, swizzled)
#define S_H2    114688   // 2 bufs x 8192
#define S_BIAS  131072   // 128 j x 2 layers x float4 (4096)
#define SMEM_SZ 135168   // 132 KB -> L1D carveout 96 KB

__device__ __forceinline__ uint32_t smem_u32(const void* p) {
    uint32_t a;
    asm("{ .reg .u64 t; cvta.to.shared.u64 t, %1; cvt.u32.u64 %0, t; }"
        : "=r"(a) : "l"(p));
    return a;
}
__device__ __forceinline__ void ldm4(uint32_t& r0, uint32_t& r1,
                                     uint32_t& r2, uint32_t& r3, uint32_t a) {
    asm volatile("ldmatrix.sync.aligned.m8n8.x4.shared.b16 {%0,%1,%2,%3}, [%4];"
                 : "=r"(r0), "=r"(r1), "=r"(r2), "=r"(r3) : "r"(a));
}
__device__ __forceinline__ void mmaf(float* d, const uint4& a,
                                     uint32_t b0, uint32_t b1) {
    asm volatile("mma.sync.aligned.m16n8k16.row.col.f32.f16.f16.f32 "
                 "{%0,%1,%2,%3}, {%4,%5,%6,%7}, {%8,%9}, {%0,%1,%2,%3};"
                 : "+f"(d[0]), "+f"(d[1]), "+f"(d[2]), "+f"(d[3])
                 : "r"(a.x), "r"(a.y), "r"(a.z), "r"(a.w), "r"(b0), "r"(b1));
}
__device__ __forceinline__ float sig_apx(float v) {
    float t;
    asm("tanh.approx.f32 %0, %1;" : "=f"(t) : "f"(v * 0.5f));
    return fmaf(t, 0.5f, 0.5f);
}
// tanh via 1 - 2/(e^{2x}+1): 2 MUFU + approx-div, exact at +-inf, no clamps
__device__ __forceinline__ float tanh_fast(float v) {
    float e2 = __expf(2.f * v);
    return 1.f - __fdividef(2.f, e2 + 1.f);
}

// ---- prep: pack fp32 weights into per-lane fp16 A fragments ---------------
__global__ void prep_kernel(const float* __restrict__ w_ih1,
                            const float* __restrict__ w_hh1,
                            const float* __restrict__ w_ih2,
                            const float* __restrict__ w_hh2) {
    int t = blockIdx.x * blockDim.x + threadIdx.x;
    if (t >= 600 * 32) return;
    int f = t >> 5, lane = t & 31;
    const float* W; uint4* dh; int K, fl;
    if (f < 24)       { W = w_ih1; dh = g_wih1H; K = 16;  fl = f; }
    else if (f < 216) { W = w_hh1; dh = g_whh1H; K = 128; fl = f - 24; }
    else if (f < 408) { W = w_ih2; dh = g_wih2H; K = 128; fl = f - 216; }
    else              { W = w_hh2; dh = g_whh2H; K = 128; fl = f - 408; }
    int nkt = K >> 4;
    int mt = fl / nkt, kt = fl % nkt;
    int gid = lane >> 2, tig = lane & 3;
    int r0 = mt * 16 + gid, r1 = r0 + 8, c0 = kt * 16 + tig * 2;
    float2 v[4];
    v[0] = *(const float2*)(W + r0 * K + c0);
    v[1] = *(const float2*)(W + r1 * K + c0);
    v[2] = *(const float2*)(W + r0 * K + c0 + 8);
    v[3] = *(const float2*)(W + r1 * K + c0 + 8);
    uint4 oh;
    uint32_t* ph = (uint32_t*)&oh;
#pragma unroll
    for (int qq = 0; qq < 4; qq++) {
        __half2 hi = __floats2half2_rn(v[qq].x, v[qq].y);
        ph[qq] = *(uint32_t*)&hi;
    }
    dh[fl * 32 + lane] = oh;
}

// ---------------------------------------------------------------------------
__global__ __launch_bounds__(NTHR, 1)
void gru_mma_kernel(const float* __restrict__ x,
                    const float* __restrict__ b_ih1, const float* __restrict__ b_hh1,
                    const float* __restrict__ b_ih2, const float* __restrict__ b_hh2,
                    const float* __restrict__ fc_w,  const float* __restrict__ fc_b,
                    float* __restrict__ out) {
    extern __shared__ char smem[];
    const uint32_t sb = smem_u32(smem);
    const int tid = threadIdx.x;
    const int wid = tid >> 5, lane = tid & 31;
    const int wpair = wid & 7;           // gate row-group (rows 16*wpair)
    const int shalf = wid >> 3;          // sample half
    const int b0 = blockIdx.x * MB;
    const int gid = lane >> 2, tig = lane & 3;
    const int lr = lane & 7, lh = (lane >> 3) & 1;
    const int nsel = lane >> 4;
    const int xorv = lr << 4;
    const int wbase = wpair * 16;
    const int ntb = shalf * 2;           // this warp's two n-tiles
    const int barid = 1 + shalf;

#define BARH() asm volatile("bar.sync %0, 256;" :: "r"(barid) : "memory")

    uint32_t h1rd = S_H1 + 8192, h1wr = S_H1;
    uint32_t h2rd = S_H2 + 8192, h2wr = S_H2;

    // ---- init: whh2 -> SMEM, zero h buffers, fp32 bias table ----
    {
        uint4* d2 = (uint4*)(smem + S_WHH2);
        for (int i = tid; i < 192 * 32; i += NTHR) d2[i] = g_whh2H[i];
        uint4 z4 = make_uint4(0, 0, 0, 0);
        uint4* hz = (uint4*)(smem + S_H1);
        for (int i = tid; i < 32768 / 16; i += NTHR) hz[i] = z4;
    }
    if (tid < 256) {
        int j = tid >> 1, layer = tid & 1;
        const float* bih = layer ? b_ih2 : b_ih1;
        const float* bhh = layer ? b_hh2 : b_hh1;
        float4 bb = make_float4(bih[j] + bhh[j], bih[128 + j] + bhh[128 + j],
                                bih[256 + j], bhh[256 + j]);
        *(float4*)(smem + S_BIAS + (j * 2 + layer) * 16) = bb;
    }

    // x B-fragments in registers: tile ntb+ntl, sample (ntb+ntl)*8+gid
    const float* xA = x + (size_t)(b0 + ntb * 8 + gid) * 2048 + 2 * tig;
    uint32_t xb0[2], xb1[2];
#pragma unroll
    for (int ntl = 0; ntl < 2; ntl++) {
        const float* p = xA + ntl * 16384;
        float2 v0 = *(const float2*)(p);
        float2 v1 = *(const float2*)(p + 1024);
        __half2 q0 = __floats2half2_rn(v0.x, v0.y);
        __half2 q1 = __floats2half2_rn(v1.x, v1.y);
        xb0[ntl] = *(uint32_t*)&q0;
        xb1[ntl] = *(uint32_t*)&q1;
    }

    float h1reg[8], h2reg[8];
#pragma unroll
    for (int e = 0; e < 8; e++) { h1reg[e] = 0.f; h2reg[e] = 0.f; }
    float ar[2][4], az[2][4], ai[2][4], ah[2][4];
    __syncthreads();

#define ZERO_ACC() { _Pragma("unroll") for (int n_ = 0; n_ < 2; n_++) \
    _Pragma("unroll") for (int e_ = 0; e_ < 4; e_++) { \
        ar[n_][e_] = 0.f; az[n_][e_] = 0.f; ai[n_][e_] = 0.f; ah[n_][e_] = 0.f; } }

// gate math + h update (h_old in regs) + fp16 store to hwr_
#define EPILOGUE(layer_, hreg_, hwr_) { \
    float4 bb0 = *(float4*)(smem + S_BIAS + ((wbase + gid) * 2 + (layer_)) * 16); \
    float4 bb1 = *(float4*)(smem + S_BIAS + ((wbase + gid + 8) * 2 + (layer_)) * 16); \
    _Pragma("unroll") for (int ntl = 0; ntl < 2; ntl++) \
    _Pragma("unroll") for (int e_ = 0; e_ < 4; e_++) { \
        const float4& bb = (e_ >> 1) ? bb1 : bb0; \
        int m_ = (ntb + ntl) * 8 + tig * 2 + (e_ & 1); \
        float r_ = sig_apx(ar[ntl][e_] + bb.x); \
        float z_ = sig_apx(az[ntl][e_] + bb.y); \
        float n_ = tanh_fast(fmaf(r_, ah[ntl][e_] + bb.w, ai[ntl][e_] + bb.z)); \
        int idx_ = ntl * 4 + e_; \
        float h_ = n_ + z_ * (hreg_[idx_] - n_); \
        hreg_[idx_] = h_; \
        int j_ = wbase + gid + (e_ >> 1) * 8; \
        uint32_t off_ = (hwr_) + m_ * 256 + ((2 * j_) ^ ((m_ & 7) << 4)); \
        *(__half*)(smem + off_) = __float2half_rn(h_); \
    } }

    const uint4* wf2 = (const uint4*)(smem + S_WHH2);

#pragma unroll 1
    for (int t = 0; t < LSEQ; t++) {
        ZERO_ACC();
        // issue wih1 loads early (L1-cached); whh1 loop below covers latency
        uint4 Ar1 = g_wih1H[wpair * 32 + lane];
        uint4 Az1 = g_wih1H[(8 + wpair) * 32 + lane];
        uint4 Ai1 = g_wih1H[(16 + wpair) * 32 + lane];
        // ---- L1: whh1 @ h1(t-1) (L1-cached LDG frags; B from h1rd) ----
#pragma unroll 2
        for (int kt = 0; kt < 8; kt++) {
            uint4 Wr = g_whh1H[(wpair * 8 + kt) * 32 + lane];
            uint4 Wz = g_whh1H[((8 + wpair) * 8 + kt) * 32 + lane];
            uint4 Wn = g_whh1H[((16 + wpair) * 8 + kt) * 32 + lane];
            uint32_t a = sb + h1rd + (uint32_t)(((ntb + nsel) * 8 + lr) * 256)
                       + (uint32_t)((kt * 32 + lh * 16) ^ xorv);
            uint32_t c0, c1, c2, c3;
            ldm4(c0, c1, c2, c3, a);
            mmaf(ar[0], Wr, c0, c1); mmaf(az[0], Wz, c0, c1); mmaf(ah[0], Wn, c0, c1);
            mmaf(ar[1], Wr, c2, c3); mmaf(az[1], Wz, c2, c3); mmaf(ah[1], Wn, c2, c3);
        }
        // ---- L1: wih1 @ x ----
#pragma unroll
        for (int ntl = 0; ntl < 2; ntl++) {
            mmaf(ar[ntl], Ar1, xb0[ntl], xb1[ntl]);
            mmaf(az[ntl], Az1, xb0[ntl], xb1[ntl]);
            mmaf(ai[ntl], Ai1, xb0[ntl], xb1[ntl]);
        }
        EPILOGUE(0, h1reg, h1wr);
        // prefetch x(t+1) into registers
        {
            int tt = (t + 1 < LSEQ) ? t + 1 : t;
#pragma unroll
            for (int ntl = 0; ntl < 2; ntl++) {
                const float* p = xA + ntl * 16384 + tt * 8;
                float2 v0 = *(const float2*)(p);
                float2 v1 = *(const float2*)(p + 1024);
                __half2 q0 = __floats2half2_rn(v0.x, v0.y);
                __half2 q1 = __floats2half2_rn(v1.x, v1.y);
                xb0[ntl] = *(uint32_t*)&q0;
                xb1[ntl] = *(uint32_t*)&q1;
            }
        }
        // ---- L2 part 1 (barrier shadow): whh2(SMEM) @ h2(t-1) ----
        ZERO_ACC();
        // prefetch wih2 kt=0 frags (.cg) for the post-barrier section
        uint4 Br = __ldcg(&g_wih2H[(wpair * 8) * 32 + lane]);
        uint4 Bz = __ldcg(&g_wih2H[((8 + wpair) * 8) * 32 + lane]);
        uint4 Bi = __ldcg(&g_wih2H[((16 + wpair) * 8) * 32 + lane]);
#pragma unroll 2
        for (int kt = 0; kt < 8; kt++) {
            uint4 Cr = wf2[(wpair * 8 + kt) * 32 + lane];
            uint4 Cz = wf2[((8 + wpair) * 8 + kt) * 32 + lane];
            uint4 Cn = wf2[((16 + wpair) * 8 + kt) * 32 + lane];
            uint32_t a2 = sb + h2rd + (uint32_t)(((ntb + nsel) * 8 + lr) * 256)
                        + (uint32_t)((kt * 32 + lh * 16) ^ xorv);
            uint32_t c0, c1, c2, c3;
            ldm4(c0, c1, c2, c3, a2);
            mmaf(ar[0], Cr, c0, c1); mmaf(az[0], Cz, c0, c1); mmaf(ah[0], Cn, c0, c1);
            mmaf(ar[1], Cr, c2, c3); mmaf(az[1], Cz, c2, c3); mmaf(ah[1], Cn, c2, c3);
        }
        BARH();   // publishes h1wr within half
        // ---- L2 part 2: wih2(.cg, pipelined) @ h1(t) ----
#pragma unroll 2
        for (int kt = 0; kt < 8; kt++) {
            uint4 Nr, Nz, Ni;
            if (kt < 7) {
                Nr = __ldcg(&g_wih2H[(wpair * 8 + kt + 1) * 32 + lane]);
                Nz = __ldcg(&g_wih2H[((8 + wpair) * 8 + kt + 1) * 32 + lane]);
                Ni = __ldcg(&g_wih2H[((16 + wpair) * 8 + kt + 1) * 32 + lane]);
            }
            uint32_t a1 = sb + h1wr + (uint32_t)(((ntb + nsel) * 8 + lr) * 256)
                        + (uint32_t)((kt * 32 + lh * 16) ^ xorv);
            uint32_t d0, d1, d2, d3;
            ldm4(d0, d1, d2, d3, a1);
            mmaf(ar[0], Br, d0, d1); mmaf(az[0], Bz, d0, d1); mmaf(ai[0], Bi, d0, d1);
            mmaf(ar[1], Br, d2, d3); mmaf(az[1], Bz, d2, d3); mmaf(ai[1], Bi, d2, d3);
            if (kt < 7) { Br = Nr; Bz = Nz; Bi = Ni; }
        }
        EPILOGUE(1, h2reg, h2wr);
        BARH();   // publishes h2wr within half (read pre-barrier next step)
        {
            uint32_t s;
            s = h1rd; h1rd = h1wr; h1wr = s;
            s = h2rd; h2rd = h2wr; h2wr = s;
        }
    }

    // ---- FC head ----
    __syncthreads();
    float* hs = (float*)smem;                  // [32][128] fp32 over whh2 region
#pragma unroll
    for (int ntl = 0; ntl < 2; ntl++)
#pragma unroll
        for (int e = 0; e < 4; e++) {
            int m = (ntb + ntl) * 8 + tig * 2 + (e & 1);
            int j = wbase + gid + (e >> 1) * 8;
            hs[m * 128 + j] = h2reg[ntl * 4 + e];
        }
    __syncthreads();
    if (tid < 256) {
        int o0 = tid * 3;
#pragma unroll
        for (int o = o0; o < o0 + 3; o++) {
            int m = o / NCLS, c = o - (o / NCLS) * NCLS;
            float acc = fc_b[c];
#pragma unroll 4
            for (int k = 0; k < HID; k++)
                acc = fmaf(fc_w[c * HID + k], hs[m * 128 + k], acc);
            out[(size_t)(b0 + m) * NCLS + c] = acc;
        }
    }
#undef BARH
#undef ZERO_ACC
#undef EPILOGUE
}

// ---------------------------------------------------------------------------
extern "C" void kernel_launch(void* const* d_in, const int* in_sizes, int n_in,
                              void* d_out, int out_size) {
    const float* x     = (const float*)d_in[0];
    const float* w_ih1 = (const float*)d_in[1];
    const float* w_hh1 = (const float*)d_in[2];
    const float* b_ih1 = (const float*)d_in[3];
    const float* b_hh1 = (const float*)d_in[4];
    const float* w_ih2 = (const float*)d_in[5];
    const float* w_hh2 = (const float*)d_in[6];
    const float* b_ih2 = (const float*)d_in[7];
    const float* b_hh2 = (const float*)d_in[8];
    const float* fc_w  = (const float*)d_in[9];
    const float* fc_b  = (const float*)d_in[10];
    float* out = (float*)d_out;

    cudaFuncSetAttribute(gru_mma_kernel,
                         cudaFuncAttributeMaxDynamicSharedMemorySize, SMEM_SZ);

    prep_kernel<<<75, 256>>>(w_ih1, w_hh1, w_ih2, w_hh2);
    gru_mma_kernel<<<4096 / MB, NTHR, SMEM_SZ>>>(x, b_ih1, b_hh1, b_ih2, b_hh2,
                                                 fc_w, fc_b, out);
}

// round 15
// speedup vs baseline: 1.9458x; 1.2220x over previous
#include <cuda_runtime.h>
#include <cuda_fp16.h>
#include <cstdint>

// ---------------------------------------------------------------------------
// GRU via mma.sync (HMMA). 128 CTAs x 256 thr (8 warps), 32 samples/CTA.
// R15: register-resident whh1 frags (24 x uint4 = 96 regs/thread, loaded
// once) — zero whh1 memory traffic in the loop. Warp w owns gate rows 16w
// for ALL 32 samples (4 n-tiles, 64 accumulator regs). whh2 SMEM-resident
// (LDS.128), wih2 streamed .cg (pipelined), wih1 L1-cached LDG.
// h_old read from fp16 tile (saves 64 regs). 2 __syncthreads per step;
// whh2@h2(t-1) block runs in the barrier shadow. SMEM 132KB -> L1D 96KB.
// ---------------------------------------------------------------------------

#define HID  128
#define MB   32
#define LSEQ 128
#define NCLS 24
#define NTHR 256

// A-fragment arrays: [frag][lane] uint4, frag = mt*8 + kt (mt = gate*8 + w)
__device__ uint4 g_wih1H[24 * 32];     // K=16, L1-cached LDG
__device__ uint4 g_whh1H[192 * 32];    // -> REGISTERS (loaded once)
__device__ uint4 g_wih2H[192 * 32];    // streamed via .cg (pipelined)
__device__ uint4 g_whh2H[192 * 32];    // -> SMEM resident

// SMEM byte offsets
#define S_WHH2  0        // whh2 frags (98304)
#define S_H1    98304    // 2 bufs x 8192 (32x128 fp16, swizzled)
#define S_H2    114688   // 2 bufs x 8192
#define S_BIAS  131072   // 128 j x 2 layers x float4 (4096)
#define SMEM_SZ 135168   // 132 KB -> L1D carveout 96 KB

__device__ __forceinline__ uint32_t smem_u32(const void* p) {
    uint32_t a;
    asm("{ .reg .u64 t; cvta.to.shared.u64 t, %1; cvt.u32.u64 %0, t; }"
        : "=r"(a) : "l"(p));
    return a;
}
__device__ __forceinline__ void ldm4(uint32_t& r0, uint32_t& r1,
                                     uint32_t& r2, uint32_t& r3, uint32_t a) {
    asm volatile("ldmatrix.sync.aligned.m8n8.x4.shared.b16 {%0,%1,%2,%3}, [%4];"
                 : "=r"(r0), "=r"(r1), "=r"(r2), "=r"(r3) : "r"(a));
}
__device__ __forceinline__ void mmaf(float* d, const uint4& a,
                                     uint32_t b0, uint32_t b1) {
    asm volatile("mma.sync.aligned.m16n8k16.row.col.f32.f16.f16.f32 "
                 "{%0,%1,%2,%3}, {%4,%5,%6,%7}, {%8,%9}, {%0,%1,%2,%3};"
                 : "+f"(d[0]), "+f"(d[1]), "+f"(d[2]), "+f"(d[3])
                 : "r"(a.x), "r"(a.y), "r"(a.z), "r"(a.w), "r"(b0), "r"(b1));
}
__device__ __forceinline__ float sig_apx(float v) {
    float t;
    asm("tanh.approx.f32 %0, %1;" : "=f"(t) : "f"(v * 0.5f));
    return fmaf(t, 0.5f, 0.5f);
}
__device__ __forceinline__ float tanh_fast(float v) {
    float e2 = __expf(2.f * v);
    return 1.f - __fdividef(2.f, e2 + 1.f);
}

// ---- prep: pack fp32 weights into per-lane fp16 A fragments ---------------
__global__ void prep_kernel(const float* __restrict__ w_ih1,
                            const float* __restrict__ w_hh1,
                            const float* __restrict__ w_ih2,
                            const float* __restrict__ w_hh2) {
    int t = blockIdx.x * blockDim.x + threadIdx.x;
    if (t >= 600 * 32) return;
    int f = t >> 5, lane = t & 31;
    const float* W; uint4* dh; int K, fl;
    if (f < 24)       { W = w_ih1; dh = g_wih1H; K = 16;  fl = f; }
    else if (f < 216) { W = w_hh1; dh = g_whh1H; K = 128; fl = f - 24; }
    else if (f < 408) { W = w_ih2; dh = g_wih2H; K = 128; fl = f - 216; }
    else              { W = w_hh2; dh = g_whh2H; K = 128; fl = f - 408; }
    int nkt = K >> 4;
    int mt = fl / nkt, kt = fl % nkt;
    int gid = lane >> 2, tig = lane & 3;
    int r0 = mt * 16 + gid, r1 = r0 + 8, c0 = kt * 16 + tig * 2;
    float2 v[4];
    v[0] = *(const float2*)(W + r0 * K + c0);
    v[1] = *(const float2*)(W + r1 * K + c0);
    v[2] = *(const float2*)(W + r0 * K + c0 + 8);
    v[3] = *(const float2*)(W + r1 * K + c0 + 8);
    uint4 oh;
    uint32_t* ph = (uint32_t*)&oh;
#pragma unroll
    for (int qq = 0; qq < 4; qq++) {
        __half2 hi = __floats2half2_rn(v[qq].x, v[qq].y);
        ph[qq] = *(uint32_t*)&hi;
    }
    dh[fl * 32 + lane] = oh;
}

// ---------------------------------------------------------------------------
__global__ __launch_bounds__(NTHR, 1)
void gru_mma_kernel(const float* __restrict__ x,
                    const float* __restrict__ b_ih1, const float* __restrict__ b_hh1,
                    const float* __restrict__ b_ih2, const float* __restrict__ b_hh2,
                    const float* __restrict__ fc_w,  const float* __restrict__ fc_b,
                    float* __restrict__ out) {
    extern __shared__ char smem[];
    const uint32_t sb = smem_u32(smem);
    const int tid = threadIdx.x;
    const int wid = tid >> 5, lane = tid & 31;
    const int b0 = blockIdx.x * MB;
    const int gid = lane >> 2, tig = lane & 3;
    const int lr = lane & 7, lh = (lane >> 3) & 1;
    const int nsel = lane >> 4;
    const int xorv = lr << 4;
    const int wbase = wid * 16;          // this warp's gate rows (all samples)

    uint32_t h1rd = S_H1 + 8192, h1wr = S_H1;
    uint32_t h2rd = S_H2 + 8192, h2wr = S_H2;

    // ---- init: whh2 -> SMEM, zero h buffers, fp32 bias table ----
    {
        uint4* d2 = (uint4*)(smem + S_WHH2);
        for (int i = tid; i < 192 * 32; i += NTHR) d2[i] = g_whh2H[i];
        uint4 z4 = make_uint4(0, 0, 0, 0);
        uint4* hz = (uint4*)(smem + S_H1);
        for (int i = tid; i < 32768 / 16; i += NTHR) hz[i] = z4;
    }
    if (tid < 256) {
        int j = tid >> 1, layer = tid & 1;
        const float* bih = layer ? b_ih2 : b_ih1;
        const float* bhh = layer ? b_hh2 : b_hh1;
        float4 bb = make_float4(bih[j] + bhh[j], bih[128 + j] + bhh[128 + j],
                                bih[256 + j], bhh[256 + j]);
        *(float4*)(smem + S_BIAS + (j * 2 + layer) * 16) = bb;
    }

    // ---- whh1 fragments -> registers (persistent; 24 x uint4) ----
    uint4 w1[24];
#pragma unroll
    for (int g3 = 0; g3 < 3; g3++)
#pragma unroll
        for (int kt = 0; kt < 8; kt++)
            w1[g3 * 8 + kt] = g_whh1H[((g3 * 8 + wid) * 8 + kt) * 32 + lane];

    // x B-fragments in registers: tile nt, sample nt*8+gid, feat 2tig(+8)
    const float* xA = x + (size_t)(b0 + gid) * 2048 + 2 * tig;
    uint32_t xb0[4], xb1[4];
#pragma unroll
    for (int nt = 0; nt < 4; nt++) {
        const float* p = xA + nt * 16384;
        float2 v0 = *(const float2*)(p);
        float2 v1 = *(const float2*)(p + 1024);
        __half2 q0 = __floats2half2_rn(v0.x, v0.y);
        __half2 q1 = __floats2half2_rn(v1.x, v1.y);
        xb0[nt] = *(uint32_t*)&q0;
        xb1[nt] = *(uint32_t*)&q1;
    }

    float ar[4][4], az[4][4], ai[4][4], ah[4][4];
    __syncthreads();

#define ZERO_ACC() { _Pragma("unroll") for (int n_ = 0; n_ < 4; n_++) \
    _Pragma("unroll") for (int e_ = 0; e_ < 4; e_++) { \
        ar[n_][e_] = 0.f; az[n_][e_] = 0.f; ai[n_][e_] = 0.f; ah[n_][e_] = 0.f; } }

// gate math + h update (h_old from rd tile, fp16) + fp16 store to wr tile
#define EPILOGUE(layer_, hrd_, hwr_) { \
    float4 bb0 = *(float4*)(smem + S_BIAS + ((wbase + gid) * 2 + (layer_)) * 16); \
    float4 bb1 = *(float4*)(smem + S_BIAS + ((wbase + gid + 8) * 2 + (layer_)) * 16); \
    _Pragma("unroll") for (int nt_ = 0; nt_ < 4; nt_++) \
    _Pragma("unroll") for (int e_ = 0; e_ < 4; e_++) { \
        const float4& bb = (e_ >> 1) ? bb1 : bb0; \
        int m_ = nt_ * 8 + tig * 2 + (e_ & 1); \
        int j_ = wbase + gid + (e_ >> 1) * 8; \
        uint32_t off_ = m_ * 256 + ((2 * j_) ^ ((m_ & 7) << 4)); \
        float hold_ = __half2float(*(__half*)(smem + (hrd_) + off_)); \
        float r_ = sig_apx(ar[nt_][e_] + bb.x); \
        float z_ = sig_apx(az[nt_][e_] + bb.y); \
        float n_ = tanh_fast(fmaf(r_, ah[nt_][e_] + bb.w, ai[nt_][e_] + bb.z)); \
        float h_ = n_ + z_ * (hold_ - n_); \
        *(__half*)(smem + (hwr_) + off_) = __float2half_rn(h_); \
    } }

    const uint4* wf2 = (const uint4*)(smem + S_WHH2);

#pragma unroll 1
    for (int t = 0; t < LSEQ; t++) {
        ZERO_ACC();
        // wih1 loads (L1-cached); whh1 loop covers latency
        uint4 Ar1 = g_wih1H[wid * 32 + lane];
        uint4 Az1 = g_wih1H[(8 + wid) * 32 + lane];
        uint4 Ai1 = g_wih1H[(16 + wid) * 32 + lane];
        // ---- L1: whh1(REGS) @ h1(t-1) ----
#pragma unroll
        for (int kt = 0; kt < 8; kt++) {
            uint32_t kb = (uint32_t)((kt * 32 + lh * 16) ^ xorv);
#pragma unroll
            for (int ntp = 0; ntp < 2; ntp++) {
                uint32_t a = sb + h1rd
                           + (uint32_t)(((ntp * 2 + nsel) * 8 + lr) * 256) + kb;
                uint32_t c0, c1, c2, c3;
                ldm4(c0, c1, c2, c3, a);
                int n0 = ntp * 2, n1 = n0 + 1;
                mmaf(ar[n0], w1[kt], c0, c1);      mmaf(az[n0], w1[8 + kt], c0, c1);
                mmaf(ah[n0], w1[16 + kt], c0, c1);
                mmaf(ar[n1], w1[kt], c2, c3);      mmaf(az[n1], w1[8 + kt], c2, c3);
                mmaf(ah[n1], w1[16 + kt], c2, c3);
            }
        }
        // ---- L1: wih1 @ x ----
#pragma unroll
        for (int nt = 0; nt < 4; nt++) {
            mmaf(ar[nt], Ar1, xb0[nt], xb1[nt]);
            mmaf(az[nt], Az1, xb0[nt], xb1[nt]);
            mmaf(ai[nt], Ai1, xb0[nt], xb1[nt]);
        }
        EPILOGUE(0, h1rd, h1wr);
        // prefetch x(t+1)
        {
            int tt = (t + 1 < LSEQ) ? t + 1 : t;
#pragma unroll
            for (int nt = 0; nt < 4; nt++) {
                const float* p = xA + nt * 16384 + tt * 8;
                float2 v0 = *(const float2*)(p);
                float2 v1 = *(const float2*)(p + 1024);
                __half2 q0 = __floats2half2_rn(v0.x, v0.y);
                __half2 q1 = __floats2half2_rn(v1.x, v1.y);
                xb0[nt] = *(uint32_t*)&q0;
                xb1[nt] = *(uint32_t*)&q1;
            }
        }
        // ---- L2 part 1 (barrier shadow): whh2(SMEM) @ h2(t-1) ----
        ZERO_ACC();
        uint4 Br = __ldcg(&g_wih2H[(wid * 8) * 32 + lane]);         // wih2 kt=0
        uint4 Bz = __ldcg(&g_wih2H[((8 + wid) * 8) * 32 + lane]);
        uint4 Bi = __ldcg(&g_wih2H[((16 + wid) * 8) * 32 + lane]);
#pragma unroll
        for (int kt = 0; kt < 8; kt++) {
            uint4 Cr = wf2[(wid * 8 + kt) * 32 + lane];
            uint4 Cz = wf2[((8 + wid) * 8 + kt) * 32 + lane];
            uint4 Cn = wf2[((16 + wid) * 8 + kt) * 32 + lane];
            uint32_t kb = (uint32_t)((kt * 32 + lh * 16) ^ xorv);
#pragma unroll
            for (int ntp = 0; ntp < 2; ntp++) {
                uint32_t a2 = sb + h2rd
                            + (uint32_t)(((ntp * 2 + nsel) * 8 + lr) * 256) + kb;
                uint32_t c0, c1, c2, c3;
                ldm4(c0, c1, c2, c3, a2);
                int n0 = ntp * 2, n1 = n0 + 1;
                mmaf(ar[n0], Cr, c0, c1); mmaf(az[n0], Cz, c0, c1); mmaf(ah[n0], Cn, c0, c1);
                mmaf(ar[n1], Cr, c2, c3); mmaf(az[n1], Cz, c2, c3); mmaf(ah[n1], Cn, c2, c3);
            }
        }
        __syncthreads();                 // publishes h1wr
        // ---- L2 part 2: wih2(.cg, pipelined) @ h1(t) ----
#pragma unroll
        for (int kt = 0; kt < 8; kt++) {
            uint4 Nr, Nz, Ni;
            if (kt < 7) {
                Nr = __ldcg(&g_wih2H[(wid * 8 + kt + 1) * 32 + lane]);
                Nz = __ldcg(&g_wih2H[((8 + wid) * 8 + kt + 1) * 32 + lane]);
                Ni = __ldcg(&g_wih2H[((16 + wid) * 8 + kt + 1) * 32 + lane]);
            }
            uint32_t kb = (uint32_t)((kt * 32 + lh * 16) ^ xorv);
#pragma unroll
            for (int ntp = 0; ntp < 2; ntp++) {
                uint32_t a1 = sb + h1wr
                            + (uint32_t)(((ntp * 2 + nsel) * 8 + lr) * 256) + kb;
                uint32_t d0, d1, d2, d3;
                ldm4(d0, d1, d2, d3, a1);
                int n0 = ntp * 2, n1 = n0 + 1;
                mmaf(ar[n0], Br, d0, d1); mmaf(az[n0], Bz, d0, d1); mmaf(ai[n0], Bi, d0, d1);
                mmaf(ar[n1], Br, d2, d3); mmaf(az[n1], Bz, d2, d3); mmaf(ai[n1], Bi, d2, d3);
            }
            if (kt < 7) { Br = Nr; Bz = Nz; Bi = Ni; }
        }
        EPILOGUE(1, h2rd, h2wr);
        __syncthreads();                 // publishes h2wr (shadow reads next t)
        {
            uint32_t s;
            s = h1rd; h1rd = h1wr; h1wr = s;
            s = h2rd; h2rd = h2wr; h2wr = s;
        }
    }

    // ---- FC head: final h2 (fp16) is in h2rd after last swap ----
    for (int o = tid; o < MB * NCLS; o += NTHR) {
        int m = o / NCLS, c = o - (o / NCLS) * NCLS;
        float acc = fc_b[c];
        uint32_t rowb = h2rd + m * 256;
        int sw = (m & 7) << 4;
#pragma unroll 4
        for (int k = 0; k < HID; k++) {
            float hv = __half2float(*(__half*)(smem + rowb + ((2 * k) ^ sw)));
            acc = fmaf(fc_w[c * HID + k], hv, acc);
        }
        out[(size_t)(b0 + m) * NCLS + c] = acc;
    }
#undef ZERO_ACC
#undef EPILOGUE
}

// ---------------------------------------------------------------------------
extern "C" void kernel_launch(void* const* d_in, const int* in_sizes, int n_in,
                              void* d_out, int out_size) {
    const float* x     = (const float*)d_in[0];
    const float* w_ih1 = (const float*)d_in[1];
    const float* w_hh1 = (const float*)d_in[2];
    const float* b_ih1 = (const float*)d_in[3];
    const float* b_hh1 = (const float*)d_in[4];
    const float* w_ih2 = (const float*)d_in[5];
    const float* w_hh2 = (const float*)d_in[6];
    const float* b_ih2 = (const float*)d_in[7];
    const float* b_hh2 = (const float*)d_in[8];
    const float* fc_w  = (const float*)d_in[9];
    const float* fc_b  = (const float*)d_in[10];
    float* out = (float*)d_out;

    cudaFuncSetAttribute(gru_mma_kernel,
                         cudaFuncAttributeMaxDynamicSharedMemorySize, SMEM_SZ);

    prep_kernel<<<75, 256>>>(w_ih1, w_hh1, w_ih2, w_hh2);
    gru_mma_kernel<<<4096 / MB, NTHR, SMEM_SZ>>>(x, b_ih1, b_hh1, b_ih2, b_hh2,
                                                 fc_w, fc_b, out);
}

// round 16
// speedup vs baseline: 2.1403x; 1.1000x over previous
#include <cuda_runtime.h>
#include <cuda_fp16.h>
#include <cstdint>

// ---------------------------------------------------------------------------
// GRU via mma.sync (HMMA). 128 CTAs x 256 thr (8 warps), 32 samples/CTA.
// R16 (on R15): (1) wih2 frags SMEM-resident (224KB SMEM; no in-loop LDG
// chains), (2) biases in registers (no SMEM table), (3) h carried as half2
// registers (epilogue h_old scatter-LDS removed). whh1 frags stay register-
// resident (96 regs). 2 syncs/step, whh2@h2(t-1) in barrier shadow.
// ---------------------------------------------------------------------------

#define HID  128
#define MB   32
#define LSEQ 128
#define NCLS 24
#define NTHR 256

// A-fragment arrays: [frag][lane] uint4, frag = mt*8 + kt (mt = gate*8 + w)
__device__ uint4 g_wih1H[24 * 32];     // K=16, LDG (hoisted, covered)
__device__ uint4 g_whh1H[192 * 32];    // -> REGISTERS (loaded once)
__device__ uint4 g_wih2H[192 * 32];    // -> SMEM resident
__device__ uint4 g_whh2H[192 * 32];    // -> SMEM resident

// SMEM byte offsets
#define S_WHH2  0        // whh2 frags (98304)
#define S_WIH2  98304    // wih2 frags (98304)
#define S_H1    196608   // 2 bufs x 8192 (32x128 fp16, swizzled)
#define S_H2    212992   // 2 bufs x 8192
#define SMEM_SZ 229376   // 224 KB

__device__ __forceinline__ uint32_t smem_u32(const void* p) {
    uint32_t a;
    asm("{ .reg .u64 t; cvta.to.shared.u64 t, %1; cvt.u32.u64 %0, t; }"
        : "=r"(a) : "l"(p));
    return a;
}
__device__ __forceinline__ void ldm4(uint32_t& r0, uint32_t& r1,
                                     uint32_t& r2, uint32_t& r3, uint32_t a) {
    asm volatile("ldmatrix.sync.aligned.m8n8.x4.shared.b16 {%0,%1,%2,%3}, [%4];"
                 : "=r"(r0), "=r"(r1), "=r"(r2), "=r"(r3) : "r"(a));
}
__device__ __forceinline__ void mmaf(float* d, const uint4& a,
                                     uint32_t b0, uint32_t b1) {
    asm volatile("mma.sync.aligned.m16n8k16.row.col.f32.f16.f16.f32 "
                 "{%0,%1,%2,%3}, {%4,%5,%6,%7}, {%8,%9}, {%0,%1,%2,%3};"
                 : "+f"(d[0]), "+f"(d[1]), "+f"(d[2]), "+f"(d[3])
                 : "r"(a.x), "r"(a.y), "r"(a.z), "r"(a.w), "r"(b0), "r"(b1));
}
__device__ __forceinline__ float sig_apx(float v) {
    float t;
    asm("tanh.approx.f32 %0, %1;" : "=f"(t) : "f"(v * 0.5f));
    return fmaf(t, 0.5f, 0.5f);
}
__device__ __forceinline__ float tanh_fast(float v) {
    float e2 = __expf(2.f * v);
    return 1.f - __fdividef(2.f, e2 + 1.f);
}

// ---- prep: pack fp32 weights into per-lane fp16 A fragments ---------------
__global__ void prep_kernel(const float* __restrict__ w_ih1,
                            const float* __restrict__ w_hh1,
                            const float* __restrict__ w_ih2,
                            const float* __restrict__ w_hh2) {
    int t = blockIdx.x * blockDim.x + threadIdx.x;
    if (t >= 600 * 32) return;
    int f = t >> 5, lane = t & 31;
    const float* W; uint4* dh; int K, fl;
    if (f < 24)       { W = w_ih1; dh = g_wih1H; K = 16;  fl = f; }
    else if (f < 216) { W = w_hh1; dh = g_whh1H; K = 128; fl = f - 24; }
    else if (f < 408) { W = w_ih2; dh = g_wih2H; K = 128; fl = f - 216; }
    else              { W = w_hh2; dh = g_whh2H; K = 128; fl = f - 408; }
    int nkt = K >> 4;
    int mt = fl / nkt, kt = fl % nkt;
    int gid = lane >> 2, tig = lane & 3;
    int r0 = mt * 16 + gid, r1 = r0 + 8, c0 = kt * 16 + tig * 2;
    float2 v[4];
    v[0] = *(const float2*)(W + r0 * K + c0);
    v[1] = *(const float2*)(W + r1 * K + c0);
    v[2] = *(const float2*)(W + r0 * K + c0 + 8);
    v[3] = *(const float2*)(W + r1 * K + c0 + 8);
    uint4 oh;
    uint32_t* ph = (uint32_t*)&oh;
#pragma unroll
    for (int qq = 0; qq < 4; qq++) {
        __half2 hi = __floats2half2_rn(v[qq].x, v[qq].y);
        ph[qq] = *(uint32_t*)&hi;
    }
    dh[fl * 32 + lane] = oh;
}

// ---------------------------------------------------------------------------
__global__ __launch_bounds__(NTHR, 1)
void gru_mma_kernel(const float* __restrict__ x,
                    const float* __restrict__ b_ih1, const float* __restrict__ b_hh1,
                    const float* __restrict__ b_ih2, const float* __restrict__ b_hh2,
                    const float* __restrict__ fc_w,  const float* __restrict__ fc_b,
                    float* __restrict__ out) {
    extern __shared__ char smem[];
    const uint32_t sb = smem_u32(smem);
    const int tid = threadIdx.x;
    const int wid = tid >> 5, lane = tid & 31;
    const int b0 = blockIdx.x * MB;
    const int gid = lane >> 2, tig = lane & 3;
    const int lr = lane & 7, lh = (lane >> 3) & 1;
    const int nsel = lane >> 4;
    const int xorv = lr << 4;
    const int wbase = wid * 16;          // this warp's gate rows (all samples)

    uint32_t h1rd = S_H1 + 8192, h1wr = S_H1;
    uint32_t h2rd = S_H2 + 8192, h2wr = S_H2;

    // ---- init: whh2 + wih2 -> SMEM, zero h buffers ----
    {
        uint4* d2 = (uint4*)(smem + S_WHH2);
        uint4* di = (uint4*)(smem + S_WIH2);
        for (int i = tid; i < 192 * 32; i += NTHR) {
            d2[i] = g_whh2H[i];
            di[i] = g_wih2H[i];
        }
        uint4 z4 = make_uint4(0, 0, 0, 0);
        uint4* hz = (uint4*)(smem + S_H1);
        for (int i = tid; i < 32768 / 16; i += NTHR) hz[i] = z4;
    }

    // ---- biases in registers ----
    const int j0 = wbase + gid, j1 = j0 + 8;
    const float4 B10 = make_float4(b_ih1[j0] + b_hh1[j0],
                                   b_ih1[128 + j0] + b_hh1[128 + j0],
                                   b_ih1[256 + j0], b_hh1[256 + j0]);
    const float4 B11 = make_float4(b_ih1[j1] + b_hh1[j1],
                                   b_ih1[128 + j1] + b_hh1[128 + j1],
                                   b_ih1[256 + j1], b_hh1[256 + j1]);
    const float4 B20 = make_float4(b_ih2[j0] + b_hh2[j0],
                                   b_ih2[128 + j0] + b_hh2[128 + j0],
                                   b_ih2[256 + j0], b_hh2[256 + j0]);
    const float4 B21 = make_float4(b_ih2[j1] + b_hh2[j1],
                                   b_ih2[128 + j1] + b_hh2[128 + j1],
                                   b_ih2[256 + j1], b_hh2[256 + j1]);

    // ---- whh1 fragments -> registers (persistent; 24 x uint4) ----
    uint4 w1[24];
#pragma unroll
    for (int g3 = 0; g3 < 3; g3++)
#pragma unroll
        for (int kt = 0; kt < 8; kt++)
            w1[g3 * 8 + kt] = g_whh1H[((g3 * 8 + wid) * 8 + kt) * 32 + lane];

    // x B-fragments in registers: tile nt, sample nt*8+gid, feat 2tig(+8)
    const float* xA = x + (size_t)(b0 + gid) * 2048 + 2 * tig;
    uint32_t xb0[4], xb1[4];
#pragma unroll
    for (int nt = 0; nt < 4; nt++) {
        const float* p = xA + nt * 16384;
        float2 v0 = *(const float2*)(p);
        float2 v1 = *(const float2*)(p + 1024);
        __half2 q0 = __floats2half2_rn(v0.x, v0.y);
        __half2 q1 = __floats2half2_rn(v1.x, v1.y);
        xb0[nt] = *(uint32_t*)&q0;
        xb1[nt] = *(uint32_t*)&q1;
    }

    // h state in half2 registers (pair p = nt*2 + rowi holds m-even/odd)
    uint32_t h1h[8], h2h[8];
#pragma unroll
    for (int p = 0; p < 8; p++) { h1h[p] = 0u; h2h[p] = 0u; }

    float ar[4][4], az[4][4], ai[4][4], ah[4][4];
    __syncthreads();

#define ZERO_ACC() { _Pragma("unroll") for (int n_ = 0; n_ < 4; n_++) \
    _Pragma("unroll") for (int e_ = 0; e_ < 4; e_++) { \
        ar[n_][e_] = 0.f; az[n_][e_] = 0.f; ai[n_][e_] = 0.f; ah[n_][e_] = 0.f; } }

// gate math + h update (h_old in half2 regs) + fp16 store to wr tile
#define EPILOGUE(B0_, B1_, hh_, hwr_) { \
    _Pragma("unroll") for (int nt_ = 0; nt_ < 4; nt_++) \
    _Pragma("unroll") for (int ri_ = 0; ri_ < 2; ri_++) { \
        const float4& bb = ri_ ? (B1_) : (B0_); \
        int p_ = nt_ * 2 + ri_; \
        float2 hold_ = __half22float2(*(__half2*)&hh_[p_]); \
        int jj_ = wbase + gid + ri_ * 8; \
        int m0_ = nt_ * 8 + tig * 2; \
        float hn_[2]; \
        _Pragma("unroll") for (int s_ = 0; s_ < 2; s_++) { \
            int e_ = ri_ * 2 + s_; \
            int m_ = m0_ + s_; \
            float r_ = sig_apx(ar[nt_][e_] + bb.x); \
            float z_ = sig_apx(az[nt_][e_] + bb.y); \
            float n_ = tanh_fast(fmaf(r_, ah[nt_][e_] + bb.w, ai[nt_][e_] + bb.z)); \
            float ho_ = s_ ? hold_.y : hold_.x; \
            float h_ = n_ + z_ * (ho_ - n_); \
            hn_[s_] = h_; \
            uint32_t off_ = (hwr_) + m_ * 256 + ((2 * jj_) ^ ((m_ & 7) << 4)); \
            *(__half*)(smem + off_) = __float2half_rn(h_); \
        } \
        __half2 nh_ = __floats2half2_rn(hn_[0], hn_[1]); \
        hh_[p_] = *(uint32_t*)&nh_; \
    } }

    const uint4* wf2  = (const uint4*)(smem + S_WHH2);
    const uint4* wfi2 = (const uint4*)(smem + S_WIH2);

#pragma unroll 1
    for (int t = 0; t < LSEQ; t++) {
        ZERO_ACC();
        // wih1 loads (global, hoisted; whh1 loop covers latency)
        uint4 Ar1 = g_wih1H[wid * 32 + lane];
        uint4 Az1 = g_wih1H[(8 + wid) * 32 + lane];
        uint4 Ai1 = g_wih1H[(16 + wid) * 32 + lane];
        // ---- L1: whh1(REGS) @ h1(t-1) ----
#pragma unroll
        for (int kt = 0; kt < 8; kt++) {
            uint32_t kb = (uint32_t)((kt * 32 + lh * 16) ^ xorv);
#pragma unroll
            for (int ntp = 0; ntp < 2; ntp++) {
                uint32_t a = sb + h1rd
                           + (uint32_t)(((ntp * 2 + nsel) * 8 + lr) * 256) + kb;
                uint32_t c0, c1, c2, c3;
                ldm4(c0, c1, c2, c3, a);
                int n0 = ntp * 2, n1 = n0 + 1;
                mmaf(ar[n0], w1[kt], c0, c1);      mmaf(az[n0], w1[8 + kt], c0, c1);
                mmaf(ah[n0], w1[16 + kt], c0, c1);
                mmaf(ar[n1], w1[kt], c2, c3);      mmaf(az[n1], w1[8 + kt], c2, c3);
                mmaf(ah[n1], w1[16 + kt], c2, c3);
            }
        }
        // ---- L1: wih1 @ x ----
#pragma unroll
        for (int nt = 0; nt < 4; nt++) {
            mmaf(ar[nt], Ar1, xb0[nt], xb1[nt]);
            mmaf(az[nt], Az1, xb0[nt], xb1[nt]);
            mmaf(ai[nt], Ai1, xb0[nt], xb1[nt]);
        }
        EPILOGUE(B10, B11, h1h, h1wr);
        // prefetch x(t+1)
        {
            int tt = (t + 1 < LSEQ) ? t + 1 : t;
#pragma unroll
            for (int nt = 0; nt < 4; nt++) {
                const float* p = xA + nt * 16384 + tt * 8;
                float2 v0 = *(const float2*)(p);
                float2 v1 = *(const float2*)(p + 1024);
                __half2 q0 = __floats2half2_rn(v0.x, v0.y);
                __half2 q1 = __floats2half2_rn(v1.x, v1.y);
                xb0[nt] = *(uint32_t*)&q0;
                xb1[nt] = *(uint32_t*)&q1;
            }
        }
        // ---- L2 part 1 (barrier shadow): whh2(SMEM) @ h2(t-1) ----
        ZERO_ACC();
#pragma unroll
        for (int kt = 0; kt < 8; kt++) {
            uint4 Cr = wf2[(wid * 8 + kt) * 32 + lane];
            uint4 Cz = wf2[((8 + wid) * 8 + kt) * 32 + lane];
            uint4 Cn = wf2[((16 + wid) * 8 + kt) * 32 + lane];
            uint32_t kb = (uint32_t)((kt * 32 + lh * 16) ^ xorv);
#pragma unroll
            for (int ntp = 0; ntp < 2; ntp++) {
                uint32_t a2 = sb + h2rd
                            + (uint32_t)(((ntp * 2 + nsel) * 8 + lr) * 256) + kb;
                uint32_t c0, c1, c2, c3;
                ldm4(c0, c1, c2, c3, a2);
                int n0 = ntp * 2, n1 = n0 + 1;
                mmaf(ar[n0], Cr, c0, c1); mmaf(az[n0], Cz, c0, c1); mmaf(ah[n0], Cn, c0, c1);
                mmaf(ar[n1], Cr, c2, c3); mmaf(az[n1], Cz, c2, c3); mmaf(ah[n1], Cn, c2, c3);
            }
        }
        __syncthreads();                 // publishes h1wr
        // ---- L2 part 2: wih2(SMEM) @ h1(t) ----
#pragma unroll
        for (int kt = 0; kt < 8; kt++) {
            uint4 Br = wfi2[(wid * 8 + kt) * 32 + lane];
            uint4 Bz = wfi2[((8 + wid) * 8 + kt) * 32 + lane];
            uint4 Bi = wfi2[((16 + wid) * 8 + kt) * 32 + lane];
            uint32_t kb = (uint32_t)((kt * 32 + lh * 16) ^ xorv);
#pragma unroll
            for (int ntp = 0; ntp < 2; ntp++) {
                uint32_t a1 = sb + h1wr
                            + (uint32_t)(((ntp * 2 + nsel) * 8 + lr) * 256) + kb;
                uint32_t d0, d1, d2, d3;
                ldm4(d0, d1, d2, d3, a1);
                int n0 = ntp * 2, n1 = n0 + 1;
                mmaf(ar[n0], Br, d0, d1); mmaf(az[n0], Bz, d0, d1); mmaf(ai[n0], Bi, d0, d1);
                mmaf(ar[n1], Br, d2, d3); mmaf(az[n1], Bz, d2, d3); mmaf(ai[n1], Bi, d2, d3);
            }
        }
        EPILOGUE(B20, B21, h2h, h2wr);
        __syncthreads();                 // publishes h2wr (shadow reads next t)
        {
            uint32_t s;
            s = h1rd; h1rd = h1wr; h1wr = s;
            s = h2rd; h2rd = h2wr; h2wr = s;
        }
    }

    // ---- FC head: final h2 (fp16) is in h2rd after last swap ----
    for (int o = tid; o < MB * NCLS; o += NTHR) {
        int m = o / NCLS, c = o - (o / NCLS) * NCLS;
        float acc = fc_b[c];
        uint32_t rowb = h2rd + m * 256;
        int sw = (m & 7) << 4;
#pragma unroll 4
        for (int k = 0; k < HID; k++) {
            float hv = __half2float(*(__half*)(smem + rowb + ((2 * k) ^ sw)));
            acc = fmaf(fc_w[c * HID + k], hv, acc);
        }
        out[(size_t)(b0 + m) * NCLS + c] = acc;
    }
#undef ZERO_ACC
#undef EPILOGUE
}

// ---------------------------------------------------------------------------
extern "C" void kernel_launch(void* const* d_in, const int* in_sizes, int n_in,
                              void* d_out, int out_size) {
    const float* x     = (const float*)d_in[0];
    const float* w_ih1 = (const float*)d_in[1];
    const float* w_hh1 = (const float*)d_in[2];
    const float* b_ih1 = (const float*)d_in[3];
    const float* b_hh1 = (const float*)d_in[4];
    const float* w_ih2 = (const float*)d_in[5];
    const float* w_hh2 = (const float*)d_in[6];
    const float* b_ih2 = (const float*)d_in[7];
    const float* b_hh2 = (const float*)d_in[8];
    const float* fc_w  = (const float*)d_in[9];
    const float* fc_b  = (const float*)d_in[10];
    float* out = (float*)d_out;

    cudaFuncSetAttribute(gru_mma_kernel,
                         cudaFuncAttributeMaxDynamicSharedMemorySize, SMEM_SZ);

    prep_kernel<<<75, 256>>>(w_ih1, w_hh1, w_ih2, w_hh2);
    gru_mma_kernel<<<4096 / MB, NTHR, SMEM_SZ>>>(x, b_ih1, b_hh1, b_ih2, b_hh2,
                                                 fc_w, fc_b, out);
}

// round 17
// speedup vs baseline: 2.3141x; 1.0812x over previous
#include <cuda_runtime.h>
#include <cuda_fp16.h>
#include <cstdint>

// ---------------------------------------------------------------------------
// GRU via mma.sync (HMMA). 128 CTAs x 256 thr (8 warps), 32 samples/CTA.
// R17 (on R16): (1) n-gate via tanh.approx.f32 (MUFU 4->3 per element,
// shorter chain), (2) wih1 fragments persistent in registers, (3) SMEM
// weight-frag LDS software-pipelined one kt ahead in both L2-phase loops.
// whh1 frags register-resident; whh2+wih2 SMEM-resident; h in half2 regs;
// 2 syncs/step with whh2@h2(t-1) in the barrier shadow. SMEM 224 KB.
// ---------------------------------------------------------------------------

#define HID  128
#define MB   32
#define LSEQ 128
#define NCLS 24
#define NTHR 256

// A-fragment arrays: [frag][lane] uint4, frag = mt*8 + kt (mt = gate*8 + w)
__device__ uint4 g_wih1H[24 * 32];     // K=16 -> REGISTERS (loaded once)
__device__ uint4 g_whh1H[192 * 32];    // -> REGISTERS (loaded once)
__device__ uint4 g_wih2H[192 * 32];    // -> SMEM resident
__device__ uint4 g_whh2H[192 * 32];    // -> SMEM resident

// SMEM byte offsets
#define S_WHH2  0        // whh2 frags (98304)
#define S_WIH2  98304    // wih2 frags (98304)
#define S_H1    196608   // 2 bufs x 8192 (32x128 fp16, swizzled)
#define S_H2    212992   // 2 bufs x 8192
#define SMEM_SZ 229376   // 224 KB

__device__ __forceinline__ uint32_t smem_u32(const void* p) {
    uint32_t a;
    asm("{ .reg .u64 t; cvta.to.shared.u64 t, %1; cvt.u32.u64 %0, t; }"
        : "=r"(a) : "l"(p));
    return a;
}
__device__ __forceinline__ void ldm4(uint32_t& r0, uint32_t& r1,
                                     uint32_t& r2, uint32_t& r3, uint32_t a) {
    asm volatile("ldmatrix.sync.aligned.m8n8.x4.shared.b16 {%0,%1,%2,%3}, [%4];"
                 : "=r"(r0), "=r"(r1), "=r"(r2), "=r"(r3) : "r"(a));
}
__device__ __forceinline__ void mmaf(float* d, const uint4& a,
                                     uint32_t b0, uint32_t b1) {
    asm volatile("mma.sync.aligned.m16n8k16.row.col.f32.f16.f16.f32 "
                 "{%0,%1,%2,%3}, {%4,%5,%6,%7}, {%8,%9}, {%0,%1,%2,%3};"
                 : "+f"(d[0]), "+f"(d[1]), "+f"(d[2]), "+f"(d[3])
                 : "r"(a.x), "r"(a.y), "r"(a.z), "r"(a.w), "r"(b0), "r"(b1));
}
__device__ __forceinline__ float sig_apx(float v) {
    float t;
    asm("tanh.approx.f32 %0, %1;" : "=f"(t) : "f"(v * 0.5f));
    return fmaf(t, 0.5f, 0.5f);
}
__device__ __forceinline__ float tanh_apx(float v) {
    float t;
    asm("tanh.approx.f32 %0, %1;" : "=f"(t) : "f"(v));
    return t;
}

// ---- prep: pack fp32 weights into per-lane fp16 A fragments ---------------
__global__ void prep_kernel(const float* __restrict__ w_ih1,
                            const float* __restrict__ w_hh1,
                            const float* __restrict__ w_ih2,
                            const float* __restrict__ w_hh2) {
    int t = blockIdx.x * blockDim.x + threadIdx.x;
    if (t >= 600 * 32) return;
    int f = t >> 5, lane = t & 31;
    const float* W; uint4* dh; int K, fl;
    if (f < 24)       { W = w_ih1; dh = g_wih1H; K = 16;  fl = f; }
    else if (f < 216) { W = w_hh1; dh = g_whh1H; K = 128; fl = f - 24; }
    else if (f < 408) { W = w_ih2; dh = g_wih2H; K = 128; fl = f - 216; }
    else              { W = w_hh2; dh = g_whh2H; K = 128; fl = f - 408; }
    int nkt = K >> 4;
    int mt = fl / nkt, kt = fl % nkt;
    int gid = lane >> 2, tig = lane & 3;
    int r0 = mt * 16 + gid, r1 = r0 + 8, c0 = kt * 16 + tig * 2;
    float2 v[4];
    v[0] = *(const float2*)(W + r0 * K + c0);
    v[1] = *(const float2*)(W + r1 * K + c0);
    v[2] = *(const float2*)(W + r0 * K + c0 + 8);
    v[3] = *(const float2*)(W + r1 * K + c0 + 8);
    uint4 oh;
    uint32_t* ph = (uint32_t*)&oh;
#pragma unroll
    for (int qq = 0; qq < 4; qq++) {
        __half2 hi = __floats2half2_rn(v[qq].x, v[qq].y);
        ph[qq] = *(uint32_t*)&hi;
    }
    dh[fl * 32 + lane] = oh;
}

// ---------------------------------------------------------------------------
__global__ __launch_bounds__(NTHR, 1)
void gru_mma_kernel(const float* __restrict__ x,
                    const float* __restrict__ b_ih1, const float* __restrict__ b_hh1,
                    const float* __restrict__ b_ih2, const float* __restrict__ b_hh2,
                    const float* __restrict__ fc_w,  const float* __restrict__ fc_b,
                    float* __restrict__ out) {
    extern __shared__ char smem[];
    const uint32_t sb = smem_u32(smem);
    const int tid = threadIdx.x;
    const int wid = tid >> 5, lane = tid & 31;
    const int b0 = blockIdx.x * MB;
    const int gid = lane >> 2, tig = lane & 3;
    const int lr = lane & 7, lh = (lane >> 3) & 1;
    const int nsel = lane >> 4;
    const int xorv = lr << 4;
    const int wbase = wid * 16;          // this warp's gate rows (all samples)

    uint32_t h1rd = S_H1 + 8192, h1wr = S_H1;
    uint32_t h2rd = S_H2 + 8192, h2wr = S_H2;

    // ---- init: whh2 + wih2 -> SMEM, zero h buffers ----
    {
        uint4* d2 = (uint4*)(smem + S_WHH2);
        uint4* di = (uint4*)(smem + S_WIH2);
        for (int i = tid; i < 192 * 32; i += NTHR) {
            d2[i] = g_whh2H[i];
            di[i] = g_wih2H[i];
        }
        uint4 z4 = make_uint4(0, 0, 0, 0);
        uint4* hz = (uint4*)(smem + S_H1);
        for (int i = tid; i < 32768 / 16; i += NTHR) hz[i] = z4;
    }

    // ---- biases in registers ----
    const int j0 = wbase + gid, j1 = j0 + 8;
    const float4 B10 = make_float4(b_ih1[j0] + b_hh1[j0],
                                   b_ih1[128 + j0] + b_hh1[128 + j0],
                                   b_ih1[256 + j0], b_hh1[256 + j0]);
    const float4 B11 = make_float4(b_ih1[j1] + b_hh1[j1],
                                   b_ih1[128 + j1] + b_hh1[128 + j1],
                                   b_ih1[256 + j1], b_hh1[256 + j1]);
    const float4 B20 = make_float4(b_ih2[j0] + b_hh2[j0],
                                   b_ih2[128 + j0] + b_hh2[128 + j0],
                                   b_ih2[256 + j0], b_hh2[256 + j0]);
    const float4 B21 = make_float4(b_ih2[j1] + b_hh2[j1],
                                   b_ih2[128 + j1] + b_hh2[128 + j1],
                                   b_ih2[256 + j1], b_hh2[256 + j1]);

    // ---- whh1 + wih1 fragments -> registers (persistent) ----
    uint4 w1[24];
#pragma unroll
    for (int g3 = 0; g3 < 3; g3++)
#pragma unroll
        for (int kt = 0; kt < 8; kt++)
            w1[g3 * 8 + kt] = g_whh1H[((g3 * 8 + wid) * 8 + kt) * 32 + lane];
    const uint4 Ar1 = g_wih1H[wid * 32 + lane];
    const uint4 Az1 = g_wih1H[(8 + wid) * 32 + lane];
    const uint4 Ai1 = g_wih1H[(16 + wid) * 32 + lane];

    // x B-fragments in registers: tile nt, sample nt*8+gid, feat 2tig(+8)
    const float* xA = x + (size_t)(b0 + gid) * 2048 + 2 * tig;
    uint32_t xb0[4], xb1[4];
#pragma unroll
    for (int nt = 0; nt < 4; nt++) {
        const float* p = xA + nt * 16384;
        float2 v0 = *(const float2*)(p);
        float2 v1 = *(const float2*)(p + 1024);
        __half2 q0 = __floats2half2_rn(v0.x, v0.y);
        __half2 q1 = __floats2half2_rn(v1.x, v1.y);
        xb0[nt] = *(uint32_t*)&q0;
        xb1[nt] = *(uint32_t*)&q1;
    }

    // h state in half2 registers (pair p = nt*2 + rowi holds m-even/odd)
    uint32_t h1h[8], h2h[8];
#pragma unroll
    for (int p = 0; p < 8; p++) { h1h[p] = 0u; h2h[p] = 0u; }

    float ar[4][4], az[4][4], ai[4][4], ah[4][4];
    __syncthreads();

#define ZERO_ACC() { _Pragma("unroll") for (int n_ = 0; n_ < 4; n_++) \
    _Pragma("unroll") for (int e_ = 0; e_ < 4; e_++) { \
        ar[n_][e_] = 0.f; az[n_][e_] = 0.f; ai[n_][e_] = 0.f; ah[n_][e_] = 0.f; } }

// gate math + h update (h_old in half2 regs) + fp16 store to wr tile
#define EPILOGUE(B0_, B1_, hh_, hwr_) { \
    _Pragma("unroll") for (int nt_ = 0; nt_ < 4; nt_++) \
    _Pragma("unroll") for (int ri_ = 0; ri_ < 2; ri_++) { \
        const float4& bb = ri_ ? (B1_) : (B0_); \
        int p_ = nt_ * 2 + ri_; \
        float2 hold_ = __half22float2(*(__half2*)&hh_[p_]); \
        int jj_ = wbase + gid + ri_ * 8; \
        int m0_ = nt_ * 8 + tig * 2; \
        float hn_[2]; \
        _Pragma("unroll") for (int s_ = 0; s_ < 2; s_++) { \
            int e_ = ri_ * 2 + s_; \
            int m_ = m0_ + s_; \
            float r_ = sig_apx(ar[nt_][e_] + bb.x); \
            float z_ = sig_apx(az[nt_][e_] + bb.y); \
            float n_ = tanh_apx(fmaf(r_, ah[nt_][e_] + bb.w, ai[nt_][e_] + bb.z)); \
            float ho_ = s_ ? hold_.y : hold_.x; \
            float h_ = n_ + z_ * (ho_ - n_); \
            hn_[s_] = h_; \
            uint32_t off_ = (hwr_) + m_ * 256 + ((2 * jj_) ^ ((m_ & 7) << 4)); \
            *(__half*)(smem + off_) = __float2half_rn(h_); \
        } \
        __half2 nh_ = __floats2half2_rn(hn_[0], hn_[1]); \
        hh_[p_] = *(uint32_t*)&nh_; \
    } }

    const uint4* wf2  = (const uint4*)(smem + S_WHH2);
    const uint4* wfi2 = (const uint4*)(smem + S_WIH2);

#pragma unroll 1
    for (int t = 0; t < LSEQ; t++) {
        ZERO_ACC();
        // ---- L1: whh1(REGS) @ h1(t-1) ----
#pragma unroll
        for (int kt = 0; kt < 8; kt++) {
            uint32_t kb = (uint32_t)((kt * 32 + lh * 16) ^ xorv);
#pragma unroll
            for (int ntp = 0; ntp < 2; ntp++) {
                uint32_t a = sb + h1rd
                           + (uint32_t)(((ntp * 2 + nsel) * 8 + lr) * 256) + kb;
                uint32_t c0, c1, c2, c3;
                ldm4(c0, c1, c2, c3, a);
                int n0 = ntp * 2, n1 = n0 + 1;
                mmaf(ar[n0], w1[kt], c0, c1);      mmaf(az[n0], w1[8 + kt], c0, c1);
                mmaf(ah[n0], w1[16 + kt], c0, c1);
                mmaf(ar[n1], w1[kt], c2, c3);      mmaf(az[n1], w1[8 + kt], c2, c3);
                mmaf(ah[n1], w1[16 + kt], c2, c3);
            }
        }
        // ---- L1: wih1(REGS) @ x ----
#pragma unroll
        for (int nt = 0; nt < 4; nt++) {
            mmaf(ar[nt], Ar1, xb0[nt], xb1[nt]);
            mmaf(az[nt], Az1, xb0[nt], xb1[nt]);
            mmaf(ai[nt], Ai1, xb0[nt], xb1[nt]);
        }
        EPILOGUE(B10, B11, h1h, h1wr);
        // prefetch x(t+1)
        {
            int tt = (t + 1 < LSEQ) ? t + 1 : t;
#pragma unroll
            for (int nt = 0; nt < 4; nt++) {
                const float* p = xA + nt * 16384 + tt * 8;
                float2 v0 = *(const float2*)(p);
                float2 v1 = *(const float2*)(p + 1024);
                __half2 q0 = __floats2half2_rn(v0.x, v0.y);
                __half2 q1 = __floats2half2_rn(v1.x, v1.y);
                xb0[nt] = *(uint32_t*)&q0;
                xb1[nt] = *(uint32_t*)&q1;
            }
        }
        // ---- L2 part 1 (barrier shadow): whh2(SMEM, pipelined) @ h2(t-1) --
        ZERO_ACC();
        {
            uint4 Cr = wf2[(wid * 8) * 32 + lane];
            uint4 Cz = wf2[((8 + wid) * 8) * 32 + lane];
            uint4 Cn = wf2[((16 + wid) * 8) * 32 + lane];
#pragma unroll
            for (int kt = 0; kt < 8; kt++) {
                uint4 Nr, Nz, Nn;
                if (kt < 7) {
                    Nr = wf2[(wid * 8 + kt + 1) * 32 + lane];
                    Nz = wf2[((8 + wid) * 8 + kt + 1) * 32 + lane];
                    Nn = wf2[((16 + wid) * 8 + kt + 1) * 32 + lane];
                }
                uint32_t kb = (uint32_t)((kt * 32 + lh * 16) ^ xorv);
#pragma unroll
                for (int ntp = 0; ntp < 2; ntp++) {
                    uint32_t a2 = sb + h2rd
                                + (uint32_t)(((ntp * 2 + nsel) * 8 + lr) * 256) + kb;
                    uint32_t c0, c1, c2, c3;
                    ldm4(c0, c1, c2, c3, a2);
                    int n0 = ntp * 2, n1 = n0 + 1;
                    mmaf(ar[n0], Cr, c0, c1); mmaf(az[n0], Cz, c0, c1); mmaf(ah[n0], Cn, c0, c1);
                    mmaf(ar[n1], Cr, c2, c3); mmaf(az[n1], Cz, c2, c3); mmaf(ah[n1], Cn, c2, c3);
                }
                if (kt < 7) { Cr = Nr; Cz = Nz; Cn = Nn; }
            }
        }
        __syncthreads();                 // publishes h1wr
        // ---- L2 part 2: wih2(SMEM, pipelined) @ h1(t) ----
        {
            uint4 Br = wfi2[(wid * 8) * 32 + lane];
            uint4 Bz = wfi2[((8 + wid) * 8) * 32 + lane];
            uint4 Bi = wfi2[((16 + wid) * 8) * 32 + lane];
#pragma unroll
            for (int kt = 0; kt < 8; kt++) {
                uint4 Nr, Nz, Ni;
                if (kt < 7) {
                    Nr = wfi2[(wid * 8 + kt + 1) * 32 + lane];
                    Nz = wfi2[((8 + wid) * 8 + kt + 1) * 32 + lane];
                    Ni = wfi2[((16 + wid) * 8 + kt + 1) * 32 + lane];
                }
                uint32_t kb = (uint32_t)((kt * 32 + lh * 16) ^ xorv);
#pragma unroll
                for (int ntp = 0; ntp < 2; ntp++) {
                    uint32_t a1 = sb + h1wr
                                + (uint32_t)(((ntp * 2 + nsel) * 8 + lr) * 256) + kb;
                    uint32_t d0, d1, d2, d3;
                    ldm4(d0, d1, d2, d3, a1);
                    int n0 = ntp * 2, n1 = n0 + 1;
                    mmaf(ar[n0], Br, d0, d1); mmaf(az[n0], Bz, d0, d1); mmaf(ai[n0], Bi, d0, d1);
                    mmaf(ar[n1], Br, d2, d3); mmaf(az[n1], Bz, d2, d3); mmaf(ai[n1], Bi, d2, d3);
                }
                if (kt < 7) { Br = Nr; Bz = Nz; Bi = Ni; }
            }
        }
        EPILOGUE(B20, B21, h2h, h2wr);
        __syncthreads();                 // publishes h2wr (shadow reads next t)
        {
            uint32_t s;
            s = h1rd; h1rd = h1wr; h1wr = s;
            s = h2rd; h2rd = h2wr; h2wr = s;
        }
    }

    // ---- FC head: final h2 (fp16) is in h2rd after last swap ----
    for (int o = tid; o < MB * NCLS; o += NTHR) {
        int m = o / NCLS, c = o - (o / NCLS) * NCLS;
        float acc = fc_b[c];
        uint32_t rowb = h2rd + m * 256;
        int sw = (m & 7) << 4;
#pragma unroll 4
        for (int k = 0; k < HID; k++) {
            float hv = __half2float(*(__half*)(smem + rowb + ((2 * k) ^ sw)));
            acc = fmaf(fc_w[c * HID + k], hv, acc);
        }
        out[(size_t)(b0 + m) * NCLS + c] = acc;
    }
#undef ZERO_ACC
#undef EPILOGUE
}

// ---------------------------------------------------------------------------
extern "C" void kernel_launch(void* const* d_in, const int* in_sizes, int n_in,
                              void* d_out, int out_size) {
    const float* x     = (const float*)d_in[0];
    const float* w_ih1 = (const float*)d_in[1];
    const float* w_hh1 = (const float*)d_in[2];
    const float* b_ih1 = (const float*)d_in[3];
    const float* b_hh1 = (const float*)d_in[4];
    const float* w_ih2 = (const float*)d_in[5];
    const float* w_hh2 = (const float*)d_in[6];
    const float* b_ih2 = (const float*)d_in[7];
    const float* b_hh2 = (const float*)d_in[8];
    const float* fc_w  = (const float*)d_in[9];
    const float* fc_b  = (const float*)d_in[10];
    float* out = (float*)d_out;

    cudaFuncSetAttribute(gru_mma_kernel,
                         cudaFuncAttributeMaxDynamicSharedMemorySize, SMEM_SZ);

    prep_kernel<<<75, 256>>>(w_ih1, w_hh1, w_ih2, w_hh2);
    gru_mma_kernel<<<4096 / MB, NTHR, SMEM_SZ>>>(x, b_ih1, b_hh1, b_ih2, b_hh2,
                                                 fc_w, fc_b, out);
}